// round 9
// baseline (speedup 1.0000x reference)
#include <cuda_runtime.h>
#include <cuda_bf16.h>
#include <cstdint>

typedef __nv_bfloat16 bf16;

#define Bz   32
#define Sz   128
#define Tz   127
#define Vz   32000
#define Ez   512
#define Gz   1024
#define HIz  512
#define G4z  4096
#define MR   4064   /* Tz*Bz */

// ------------------------- static device scratch -------------------------
__device__ bf16  g_Wout_hi[(size_t)Vz*Gz];
__device__ bf16  g_Wout_lo[(size_t)Vz*Gz];
__device__ bf16  g_Wih_hi[(size_t)G4z*Ez];
__device__ bf16  g_Wih_lo[(size_t)G4z*Ez];
__device__ bf16  g_Whh_hi[(size_t)G4z*Gz];
__device__ bf16  g_Whh_lo[(size_t)G4z*Gz];
__device__ bf16  g_H_hi[(size_t)(Tz+1)*Bz*Gz];  // block s = h after step s (block 0 = h0)
__device__ bf16  g_H_lo[(size_t)(Tz+1)*Bz*Gz];
__device__ bf16  g_X_hi[(size_t)MR*Ez];
__device__ bf16  g_X_lo[(size_t)MR*Ez];
__device__ float g_Xg[(size_t)MR*G4z];
__device__ float g_c[Bz*Gz];
__device__ float g_Q[Bz*HIz];
__device__ float g_Kb[Bz*16*HIz];
__device__ float g_Vb[Bz*16*HIz];
__device__ float g_ctx[Bz*HIz];
__device__ float g_att[Bz*HIz];
__device__ float g_ff[Bz*3*HIz];
__device__ float g_ie[Bz*Ez];
__device__ float g_g0[Bz*G4z];
__device__ float g_bsum[G4z];

// ------------------------------ helpers ----------------------------------
__device__ __forceinline__ float sigf(float x){ return 1.0f/(1.0f+expf(-x)); }

__device__ __forceinline__ void ldsmx4(uint32_t* r, const bf16* p){
    uint32_t a = (uint32_t)__cvta_generic_to_shared(p);
    asm volatile("ldmatrix.sync.aligned.m8n8.x4.shared.b16 {%0,%1,%2,%3},[%4];\n"
                 : "=r"(r[0]),"=r"(r[1]),"=r"(r[2]),"=r"(r[3]) : "r"(a));
}
__device__ __forceinline__ void mma16816(float* d, const uint32_t* a, const uint32_t* b){
    asm volatile("mma.sync.aligned.m16n8k16.row.col.f32.bf16.bf16.f32 "
                 "{%0,%1,%2,%3},{%4,%5,%6,%7},{%8,%9},{%0,%1,%2,%3};\n"
                 : "+f"(d[0]),"+f"(d[1]),"+f"(d[2]),"+f"(d[3])
                 : "r"(a[0]),"r"(a[1]),"r"(a[2]),"r"(a[3]),
                   "r"(b[0]),"r"(b[1]));
}

// --------------------------- prep kernels --------------------------------
__global__ void k_split(const float* __restrict__ src, bf16* __restrict__ hi,
                        bf16* __restrict__ lo, int n){
    int i = blockIdx.x*blockDim.x + threadIdx.x;
    if (i < n){
        float x = src[i];
        bf16 h = __float2bfloat16(x);
        hi[i] = h;
        lo[i] = __float2bfloat16(x - __bfloat162float(h));
    }
}

__global__ void k_bsum(const float* __restrict__ a, const float* __restrict__ b){
    int i = blockIdx.x*blockDim.x + threadIdx.x;
    if (i < G4z) g_bsum[i] = a[i] + b[i];
}

__global__ void k_xgather(const float* __restrict__ emb, const int* __restrict__ sent){
    int i = blockIdx.x*blockDim.x + threadIdx.x;
    if (i < MR*Ez){
        int r = i >> 9, col = i & 511;      // Ez = 512
        int t = r >> 5, b = r & 31;
        int idx = sent[b*Sz + t];           // x uses target_sent[:, :-1]
        float v = emb[(size_t)idx*Ez + col];
        bf16 h = __float2bfloat16(v);
        g_X_hi[i] = h;
        g_X_lo[i] = __float2bfloat16(v - __bfloat162float(h));
    }
}

__global__ void k_ff(const float* __restrict__ ent, const float* __restrict__ img){
    int i = blockIdx.x*blockDim.x + threadIdx.x;
    if (i < Bz*HIz){
        int b = i >> 9, j = i & 511;
        float* row = g_ff + (size_t)b*3*HIz;
        row[j]          = ent[i];
        row[HIz + j]    = g_att[i];
        row[2*HIz + j]  = img[i];
    }
}

// ------------------- generic small fp32 GEMM (warp/output) ---------------
// out[m*N+n] = act( sum_k A[m,k]*W[n,k] + bias[n] )
__global__ void k_small(const float* __restrict__ A, const float* __restrict__ W,
                        const float* __restrict__ bias, float* __restrict__ out,
                        int M, int N, int K, int act){
    int gw = (blockIdx.x*blockDim.x + threadIdx.x) >> 5;
    int lane = threadIdx.x & 31;
    if (gw >= M*N) return;
    int m = gw / N, n = gw % N;
    const float* a = A + (size_t)m*K;
    const float* w = W + (size_t)n*K;
    float s = 0.f;
    for (int k = lane; k < K; k += 32) s += a[k]*w[k];
#pragma unroll
    for (int o = 16; o; o >>= 1) s += __shfl_down_sync(0xffffffffu, s, o);
    if (lane == 0){
        s += bias ? bias[n] : 0.f;
        if (act == 1) s = tanhf(s);
        out[(size_t)m*N + n] = s;
    }
}

// ------------------------------ attention --------------------------------
__global__ void k_attn(const int* __restrict__ nnum){
    int bh = blockIdx.x;
    int b = bh >> 3, h = bh & 7;
    int d = threadIdx.x;                    // 64 threads
    __shared__ float red[64];
    __shared__ float sc[16];
    float q = g_Q[b*HIz + h*64 + d];
    for (int n = 0; n < 16; n++){
        red[d] = q * g_Kb[(size_t)(b*16+n)*HIz + h*64 + d];
        __syncthreads();
        for (int o = 32; o; o >>= 1){
            if (d < o) red[d] += red[d+o];
            __syncthreads();
        }
        if (d == 0) sc[n] = red[0]*0.125f;   // 1/sqrt(64)
        __syncthreads();
    }
    int num = nnum[b];
    float a[16], mx = -1e30f;
#pragma unroll
    for (int n = 0; n < 16; n++){
        a[n] = (n >= num) ? -1e9f : sc[n];
        mx = fmaxf(mx, a[n]);
    }
    float ssum = 0.f;
#pragma unroll
    for (int n = 0; n < 16; n++){ a[n] = expf(a[n]-mx); ssum += a[n]; }
    float inv = 1.f/ssum;
    float ctx = 0.f;
#pragma unroll
    for (int n = 0; n < 16; n++)
        ctx += a[n] * g_Vb[(size_t)(b*16+n)*HIz + h*64 + d];
    g_ctx[b*HIz + h*64 + d] = ctx*inv;
}

// --------------------------- first LSTM step -----------------------------
__global__ void k_step0(){
    int i = blockIdx.x*blockDim.x + threadIdx.x;
    if (i < Bz*Gz){
        int b = i >> 10, j = i & 1023;
        const float* g0 = g_g0 + (size_t)b*G4z;
        float gi = g0[j], gf = g0[j+Gz], gg = g0[j+2*Gz], go = g0[j+3*Gz];
        (void)gf; // c_prev = 0
        float c = sigf(gi)*tanhf(gg);
        float h = sigf(go)*tanhf(c);
        g_c[i] = c;
        bf16 hh = __float2bfloat16(h);
        g_H_hi[i] = hh;
        g_H_lo[i] = __float2bfloat16(h - __bfloat162float(hh));
    }
}

// ----------------- fused recurrence step (MMA + LSTM cell) ---------------
// 64 blocks x 128 threads. Block nb owns gate cols {nb*16..+15} in all 4
// quadrants (warp q = quadrant q). Computes h_prev @ W_hh^T for its 64 gate
// rows, adds precomputed Xg, applies cell update, writes h (bf16 hi/lo).
#define SLD 72
__global__ void __launch_bounds__(128, 1) k_step(int s){
    __shared__ bf16 sA[2][32*SLD];
    __shared__ bf16 sB[2][64*SLD];
    __shared__ float sG[4][32][16];
    const int tid = threadIdx.x, warp = tid >> 5, lane = tid & 31;
    const int nb = blockIdx.x;
    const bf16* hHi = g_H_hi + (size_t)s*Bz*Gz;
    const bf16* hLo = g_H_lo + (size_t)s*Bz*Gz;
    bf16* oHi = g_H_hi + (size_t)(s+1)*Bz*Gz;
    bf16* oLo = g_H_lo + (size_t)(s+1)*Bz*Gz;
    const float* Xg = g_Xg + (size_t)s*Bz*G4z;

    float acc[2][2][4];
#pragma unroll
    for (int a=0;a<2;a++)
#pragma unroll
    for (int b=0;b<2;b++)
#pragma unroll
    for (int c=0;c<4;c++) acc[a][b][c]=0.f;

    for (int kk = 0; kk < Gz; kk += 64){
#pragma unroll
        for (int i = 0; i < 2; i++){        // A: 32x64 -> 256 uint4 per matrix
            int u = tid + i*128;
            int r = u >> 3, c = (u & 7)*8;
            *(uint4*)&sA[0][r*SLD+c] = *(const uint4*)(hHi + (size_t)r*Gz + kk + c);
            *(uint4*)&sA[1][r*SLD+c] = *(const uint4*)(hLo + (size_t)r*Gz + kk + c);
        }
#pragma unroll
        for (int i = 0; i < 4; i++){        // B: 64x64 -> 512 uint4 per matrix
            int u = tid + i*128;
            int r = u >> 3, c = (u & 7)*8;
            int g = (r >> 4)*Gz + nb*16 + (r & 15);
            *(uint4*)&sB[0][r*SLD+c] = *(const uint4*)(g_Whh_hi + (size_t)g*Gz + kk + c);
            *(uint4*)&sB[1][r*SLD+c] = *(const uint4*)(g_Whh_lo + (size_t)g*Gz + kk + c);
        }
        __syncthreads();
#pragma unroll
        for (int ks = 0; ks < 64; ks += 16){
            uint32_t ah[2][4], al[2][4], bh[4], bl[4];
#pragma unroll
            for (int mi = 0; mi < 2; mi++){
                int row = mi*16 + (lane & 15);
                int kc  = ks + (lane >> 4)*8;
                ldsmx4(ah[mi], &sA[0][row*SLD + kc]);
                ldsmx4(al[mi], &sA[1][row*SLD + kc]);
            }
            {
                int j = lane >> 3;
                int row = warp*16 + ((j >> 1)*8) + (lane & 7);
                int kc  = ks + (j & 1)*8;
                ldsmx4(bh, &sB[0][row*SLD + kc]);
                ldsmx4(bl, &sB[1][row*SLD + kc]);
            }
#pragma unroll
            for (int mi = 0; mi < 2; mi++)
#pragma unroll
                for (int nj = 0; nj < 2; nj++){
                    mma16816(acc[mi][nj], ah[mi], &bh[nj*2]);
                    mma16816(acc[mi][nj], ah[mi], &bl[nj*2]);
                    mma16816(acc[mi][nj], al[mi], &bh[nj*2]);
                }
        }
        __syncthreads();
    }
    // scatter accumulators: warp q holds quadrant q values for (b, jl)
#pragma unroll
    for (int mi = 0; mi < 2; mi++)
#pragma unroll
    for (int nj = 0; nj < 2; nj++)
#pragma unroll
    for (int h = 0; h < 2; h++){
        int b  = mi*16 + (lane >> 2) + h*8;
        int jl = nj*8 + (lane & 3)*2;
        sG[warp][b][jl]   = acc[mi][nj][h*2];
        sG[warp][b][jl+1] = acc[mi][nj][h*2+1];
    }
    __syncthreads();
    // LSTM cell update for 32x16 elements
    for (int e = tid; e < 512; e += 128){
        int b = e >> 4, jl = e & 15;
        int col = nb*16 + jl;
        const float* xg = Xg + (size_t)b*G4z;
        float gi = sG[0][b][jl] + xg[col];
        float gf = sG[1][b][jl] + xg[col +   Gz];
        float gg = sG[2][b][jl] + xg[col + 2*Gz];
        float go = sG[3][b][jl] + xg[col + 3*Gz];
        float c = sigf(gf)*g_c[b*Gz+col] + sigf(gi)*tanhf(gg);
        float h = sigf(go)*tanhf(c);
        g_c[b*Gz+col] = c;
        bf16 hh = __float2bfloat16(h);
        oHi[b*Gz+col] = hh;
        oLo[b*Gz+col] = __float2bfloat16(h - __bfloat162float(hh));
    }
}

// ------------- big split-bf16 GEMM:  D = A(hi+lo) * B(hi+lo)^T ------------
// 128x128 block tile, BK=32, 8 warps (2x4), warp tile 64x32, 3 MMA terms.
// mode 0: out[m*N+n] = D + bias[n]
// mode 1: logits remap  out[(b*127+t)*N + n],  m = t*32 + b
#define LDT 40
__global__ void __launch_bounds__(256, 1) k_gemm3(
    const bf16* __restrict__ Ahi, const bf16* __restrict__ Alo,
    const bf16* __restrict__ Bhi, const bf16* __restrict__ Blo,
    const float* __restrict__ bias, float* __restrict__ out,
    int M, int N, int K, int mode)
{
    __shared__ bf16 sA[2][128*LDT];
    __shared__ bf16 sB[2][128*LDT];
    const int tid = threadIdx.x, warp = tid >> 5, lane = tid & 31;
    const int m0 = blockIdx.x*128, n0 = blockIdx.y*128;
    const int wm = (warp >> 2)*64, wn = (warp & 3)*32;

    float acc[4][4][4];
#pragma unroll
    for (int a=0;a<4;a++)
#pragma unroll
    for (int b=0;b<4;b++)
#pragma unroll
    for (int c=0;c<4;c++) acc[a][b][c]=0.f;

    for (int kk = 0; kk < K; kk += 32){
#pragma unroll
        for (int i = 0; i < 2; i++){
            int u = tid + i*256;            // 0..511
            int r = u >> 2, c = (u & 3)*8;
            int gr = m0 + r;
            uint4 vh = make_uint4(0,0,0,0), vl = make_uint4(0,0,0,0);
            if (gr < M){
                vh = *(const uint4*)(Ahi + (size_t)gr*K + kk + c);
                vl = *(const uint4*)(Alo + (size_t)gr*K + kk + c);
            }
            *(uint4*)&sA[0][r*LDT+c] = vh;
            *(uint4*)&sA[1][r*LDT+c] = vl;
            int gn = n0 + r;                // N is multiple of 128 in both uses
            *(uint4*)&sB[0][r*LDT+c] = *(const uint4*)(Bhi + (size_t)gn*K + kk + c);
            *(uint4*)&sB[1][r*LDT+c] = *(const uint4*)(Blo + (size_t)gn*K + kk + c);
        }
        __syncthreads();
#pragma unroll
        for (int ks = 0; ks < 32; ks += 16){
            uint32_t ah[4][4], al[4][4], bh[2][4], bl[2][4];
#pragma unroll
            for (int mi = 0; mi < 4; mi++){
                int row = wm + mi*16 + (lane & 15);
                int kc  = ks + (lane >> 4)*8;
                ldsmx4(ah[mi], &sA[0][row*LDT + kc]);
                ldsmx4(al[mi], &sA[1][row*LDT + kc]);
            }
#pragma unroll
            for (int ni = 0; ni < 2; ni++){
                int j = lane >> 3;
                int row = wn + ni*16 + ((j >> 1)*8) + (lane & 7);
                int kc  = ks + (j & 1)*8;
                ldsmx4(bh[ni], &sB[0][row*LDT + kc]);
                ldsmx4(bl[ni], &sB[1][row*LDT + kc]);
            }
#pragma unroll
            for (int mi = 0; mi < 4; mi++)
#pragma unroll
                for (int nj = 0; nj < 4; nj++){
                    const uint32_t* fh = &bh[nj >> 1][(nj & 1)*2];
                    const uint32_t* fl = &bl[nj >> 1][(nj & 1)*2];
                    mma16816(acc[mi][nj], ah[mi], fh);
                    mma16816(acc[mi][nj], ah[mi], fl);
                    mma16816(acc[mi][nj], al[mi], fh);
                }
        }
        __syncthreads();
    }
    // epilogue
#pragma unroll
    for (int mi = 0; mi < 4; mi++)
#pragma unroll
    for (int nj = 0; nj < 4; nj++){
        int n = n0 + wn + nj*8 + (lane & 3)*2;
        float b0 = bias[n], b1 = bias[n+1];
#pragma unroll
        for (int h = 0; h < 2; h++){
            int m = m0 + wm + mi*16 + (lane >> 2) + h*8;
            if (m < M){
                size_t off;
                if (mode == 1){
                    int t = m >> 5, b = m & 31;
                    off = ((size_t)b*Tz + t)*(size_t)N + n;
                } else {
                    off = (size_t)m*N + n;
                }
                out[off]   = acc[mi][nj][h*2]   + b0;
                out[off+1] = acc[mi][nj][h*2+1] + b1;
            }
        }
    }
}

// ------------------------------- tail ------------------------------------
__global__ void k_tail(const int* __restrict__ sent, const int* __restrict__ slen,
                       float* __restrict__ out, long out_size){
    long base = (long)Bz*Tz*Vz;             // 130048000
    int i = blockIdx.x*blockDim.x + threadIdx.x;
    if (i < Bz*Sz && base + i < out_size)            out[base+i] = (float)sent[i];
    if (i < Bz && base + Bz*Sz + i < out_size)       out[base+Bz*Sz+i] = (float)slen[i];
}

// ------------------------------ host side --------------------------------
extern "C" void kernel_launch(void* const* d_in, const int* in_sizes, int n_in,
                              void* d_out, int out_size) {
    const float* ent   = (const float*)d_in[0];
    const float* neigh = (const float*)d_in[1];
    const int*   nnum  = (const int*)  d_in[2];
    const float* img   = (const float*)d_in[3];
    const int*   sent  = (const int*)  d_in[4];
    const int*   slen  = (const int*)  d_in[5];
    const float* emb   = (const float*)d_in[6];
    const float* W_ih  = (const float*)d_in[7];
    const float* W_hh  = (const float*)d_in[8];
    const float* b_ih  = (const float*)d_in[9];
    const float* b_hh  = (const float*)d_in[10];
    const float* W_img = (const float*)d_in[11];
    const float* b_img = (const float*)d_in[12];
    const float* W_out = (const float*)d_in[13];
    const float* b_out = (const float*)d_in[14];
    const float* Wq = (const float*)d_in[15]; const float* bq = (const float*)d_in[16];
    const float* Wk = (const float*)d_in[17]; const float* bk = (const float*)d_in[18];
    const float* Wv = (const float*)d_in[19]; const float* bv = (const float*)d_in[20];
    const float* Wo = (const float*)d_in[21]; const float* bo = (const float*)d_in[22];
    float* out = (float*)d_out;

    void *pWout_hi, *pWout_lo, *pWih_hi, *pWih_lo, *pWhh_hi, *pWhh_lo;
    void *pXhi, *pXlo, *pXg, *pHhi, *pHlo, *pBsum;
    void *pQ, *pKb, *pVb, *pCtx, *pAtt, *pFf, *pIe, *pG0;
    cudaGetSymbolAddress(&pWout_hi, g_Wout_hi); cudaGetSymbolAddress(&pWout_lo, g_Wout_lo);
    cudaGetSymbolAddress(&pWih_hi,  g_Wih_hi);  cudaGetSymbolAddress(&pWih_lo,  g_Wih_lo);
    cudaGetSymbolAddress(&pWhh_hi,  g_Whh_hi);  cudaGetSymbolAddress(&pWhh_lo,  g_Whh_lo);
    cudaGetSymbolAddress(&pXhi, g_X_hi); cudaGetSymbolAddress(&pXlo, g_X_lo);
    cudaGetSymbolAddress(&pXg,  g_Xg);   cudaGetSymbolAddress(&pBsum, g_bsum);
    cudaGetSymbolAddress(&pHhi, g_H_hi); cudaGetSymbolAddress(&pHlo, g_H_lo);
    cudaGetSymbolAddress(&pQ, g_Q); cudaGetSymbolAddress(&pKb, g_Kb);
    cudaGetSymbolAddress(&pVb, g_Vb); cudaGetSymbolAddress(&pCtx, g_ctx);
    cudaGetSymbolAddress(&pAtt, g_att); cudaGetSymbolAddress(&pFf, g_ff);
    cudaGetSymbolAddress(&pIe, g_ie); cudaGetSymbolAddress(&pG0, g_g0);

    // ---- prep: split weights to bf16 hi/lo, gather+split embeddings ----
    {
        int n = Vz*Gz;
        k_split<<<(n+255)/256, 256>>>(W_out, (bf16*)pWout_hi, (bf16*)pWout_lo, n);
        n = G4z*Ez;
        k_split<<<(n+255)/256, 256>>>(W_ih, (bf16*)pWih_hi, (bf16*)pWih_lo, n);
        n = G4z*Gz;
        k_split<<<(n+255)/256, 256>>>(W_hh, (bf16*)pWhh_hi, (bf16*)pWhh_lo, n);
        k_bsum<<<(G4z+255)/256, 256>>>(b_ih, b_hh);
        n = MR*Ez;
        k_xgather<<<(n+255)/256, 256>>>(emb, sent);
    }

    // ---- prologue: MHA + img_embed + first LSTM step ----
    k_small<<<(Bz*HIz*32+255)/256, 256>>>(ent, Wq, bq, (float*)pQ, Bz, HIz, HIz, 0);
    k_small<<<(Bz*16*HIz*32+255)/256, 256>>>(neigh, Wk, bk, (float*)pKb, Bz*16, HIz, HIz, 0);
    k_small<<<(Bz*16*HIz*32+255)/256, 256>>>(neigh, Wv, bv, (float*)pVb, Bz*16, HIz, HIz, 0);
    k_attn<<<Bz*8, 64>>>(nnum);
    k_small<<<(Bz*HIz*32+255)/256, 256>>>((const float*)pCtx, Wo, bo, (float*)pAtt, Bz, HIz, HIz, 0);
    k_ff<<<(Bz*HIz+255)/256, 256>>>(ent, img);
    k_small<<<(Bz*HIz*32+255)/256, 256>>>((const float*)pFf, W_img, b_img, (float*)pIe, Bz, HIz, 3*HIz, 1);
    k_small<<<(Bz*G4z*32+255)/256, 256>>>((const float*)pIe, W_ih, (const float*)pBsum, (float*)pG0, Bz, G4z, Ez, 0);
    k_step0<<<(Bz*Gz+255)/256, 256>>>();

    // ---- Xg = X @ W_ih^T + bsum  for all 127 steps (one GEMM) ----
    {
        dim3 grid((MR+127)/128, G4z/128);
        k_gemm3<<<grid, 256>>>((const bf16*)pXhi, (const bf16*)pXlo,
                               (const bf16*)pWih_hi, (const bf16*)pWih_lo,
                               (const float*)pBsum, (float*)pXg,
                               MR, G4z, Ez, 0);
    }

    // ---- recurrence: 127 fused steps ----
    for (int s = 0; s < Tz; s++)
        k_step<<<64, 128>>>(s);

    // ---- logits: one [4064,1024] x [1024,32000] GEMM, remapped to [B,T,V] ----
    {
        dim3 grid((MR+127)/128, Vz/128);
        k_gemm3<<<grid, 256>>>((const bf16*)pHhi + Bz*Gz, (const bf16*)pHlo + Bz*Gz,
                               (const bf16*)pWout_hi, (const bf16*)pWout_lo,
                               b_out, out, MR, Vz, Gz, 1);
    }

    // ---- tuple tail (target_sent, target_sent_len) if harness expects it ----
    if ((long)out_size > (long)Bz*Tz*Vz)
        k_tail<<<(Bz*Sz+255)/256, 256>>>(sent, slen, out, (long)out_size);
}

// round 11
// speedup vs baseline: 1.1123x; 1.1123x over previous
#include <cuda_runtime.h>
#include <cuda_bf16.h>
#include <cstdint>

typedef __nv_bfloat16 bf16;

#define Bz   32
#define Sz   128
#define Tz   127
#define Vz   32000
#define Ez   512
#define Gz   1024
#define HIz  512
#define G4z  4096
#define MR   4064   /* Tz*Bz */

// ------------------------- static device scratch -------------------------
__device__ bf16  g_Wout_hi[(size_t)Vz*Gz];
__device__ bf16  g_Wout_lo[(size_t)Vz*Gz];
__device__ bf16  g_Wih_hi[(size_t)G4z*Ez];
__device__ bf16  g_Wih_lo[(size_t)G4z*Ez];
__device__ bf16  g_Whh_hi[(size_t)G4z*Gz];
__device__ bf16  g_Whh_lo[(size_t)G4z*Gz];
__device__ bf16  g_H_hi[(size_t)(Tz+2)*Bz*Gz];
__device__ bf16  g_H_lo[(size_t)(Tz+2)*Bz*Gz];
__device__ bf16  g_X_hi[(size_t)MR*Ez];
__device__ bf16  g_X_lo[(size_t)MR*Ez];
__device__ float g_Xg[(size_t)MR*G4z];
__device__ float g_c[Bz*Gz];
__device__ float g_Q[Bz*HIz];
__device__ float g_Kb[Bz*16*HIz];
__device__ float g_Vb[Bz*16*HIz];
__device__ float g_ctx[Bz*HIz];
__device__ float g_att[Bz*HIz];
__device__ float g_ff[Bz*3*HIz];
__device__ float g_ie[Bz*Ez];
__device__ float g_g0[Bz*G4z];
__device__ float g_bsum[G4z];

// ------------------------------ helpers ----------------------------------
__device__ __forceinline__ float sigf(float x){ return 1.0f/(1.0f+expf(-x)); }

__device__ __forceinline__ uint32_t smem_u32(const void* p){
    return (uint32_t)__cvta_generic_to_shared(p);
}
__device__ __forceinline__ void ldsmx4(uint32_t* r, const bf16* p){
    uint32_t a = smem_u32(p);
    asm volatile("ldmatrix.sync.aligned.m8n8.x4.shared.b16 {%0,%1,%2,%3},[%4];\n"
                 : "=r"(r[0]),"=r"(r[1]),"=r"(r[2]),"=r"(r[3]) : "r"(a));
}
__device__ __forceinline__ void mma16816(float* d, const uint32_t* a, const uint32_t* b){
    asm volatile("mma.sync.aligned.m16n8k16.row.col.f32.bf16.bf16.f32 "
                 "{%0,%1,%2,%3},{%4,%5,%6,%7},{%8,%9},{%0,%1,%2,%3};\n"
                 : "+f"(d[0]),"+f"(d[1]),"+f"(d[2]),"+f"(d[3])
                 : "r"(a[0]),"r"(a[1]),"r"(a[2]),"r"(a[3]),
                   "r"(b[0]),"r"(b[1]));
}
#define CP_ASYNC16P(dst, src, pv) \
    asm volatile("cp.async.cg.shared.global [%0], [%1], 16, %2;" \
                 :: "r"(dst), "l"(src), "r"(pv))
#define CP_ASYNC16(dst, src) \
    asm volatile("cp.async.cg.shared.global [%0], [%1], 16;" :: "r"(dst), "l"(src))
#define CP_COMMIT()  asm volatile("cp.async.commit_group;" ::: "memory")

// --------------------------- prep kernels --------------------------------
__global__ void k_split(const float* __restrict__ src, bf16* __restrict__ hi,
                        bf16* __restrict__ lo, int n){
    int i = blockIdx.x*blockDim.x + threadIdx.x;
    if (i < n){
        float x = src[i];
        bf16 h = __float2bfloat16(x);
        hi[i] = h;
        lo[i] = __float2bfloat16(x - __bfloat162float(h));
    }
}

__global__ void k_bsum(const float* __restrict__ a, const float* __restrict__ b){
    int i = blockIdx.x*blockDim.x + threadIdx.x;
    if (i < G4z) g_bsum[i] = a[i] + b[i];
}

__global__ void k_xgather(const float* __restrict__ emb, const int* __restrict__ sent){
    int i = blockIdx.x*blockDim.x + threadIdx.x;
    if (i < MR*Ez){
        int r = i >> 9, col = i & 511;
        int t = r >> 5, b = r & 31;
        int idx = sent[b*Sz + t];
        float v = emb[(size_t)idx*Ez + col];
        bf16 h = __float2bfloat16(v);
        g_X_hi[i] = h;
        g_X_lo[i] = __float2bfloat16(v - __bfloat162float(h));
    }
}

__global__ void k_ff(const float* __restrict__ ent, const float* __restrict__ img){
    int i = blockIdx.x*blockDim.x + threadIdx.x;
    if (i < Bz*HIz){
        int b = i >> 9, j = i & 511;
        float* row = g_ff + (size_t)b*3*HIz;
        row[j]          = ent[i];
        row[HIz + j]    = g_att[i];
        row[2*HIz + j]  = img[i];
    }
}

// ------------------- generic small fp32 GEMM (warp/output) ---------------
__global__ void k_small(const float* __restrict__ A, const float* __restrict__ W,
                        const float* __restrict__ bias, float* __restrict__ out,
                        int M, int N, int K, int act){
    int gw = (blockIdx.x*blockDim.x + threadIdx.x) >> 5;
    int lane = threadIdx.x & 31;
    if (gw >= M*N) return;
    int m = gw / N, n = gw % N;
    const float* a = A + (size_t)m*K;
    const float* w = W + (size_t)n*K;
    float s = 0.f;
    for (int k = lane; k < K; k += 32) s += a[k]*w[k];
#pragma unroll
    for (int o = 16; o; o >>= 1) s += __shfl_down_sync(0xffffffffu, s, o);
    if (lane == 0){
        s += bias ? bias[n] : 0.f;
        if (act == 1) s = tanhf(s);
        out[(size_t)m*N + n] = s;
    }
}

// ------------------------------ attention --------------------------------
__global__ void k_attn(const int* __restrict__ nnum){
    int bh = blockIdx.x;
    int b = bh >> 3, h = bh & 7;
    int d = threadIdx.x;                    // 64 threads
    __shared__ float red[64];
    __shared__ float sc[16];
    float q = g_Q[b*HIz + h*64 + d];
    for (int n = 0; n < 16; n++){
        red[d] = q * g_Kb[(size_t)(b*16+n)*HIz + h*64 + d];
        __syncthreads();
        for (int o = 32; o; o >>= 1){
            if (d < o) red[d] += red[d+o];
            __syncthreads();
        }
        if (d == 0) sc[n] = red[0]*0.125f;
        __syncthreads();
    }
    int num = nnum[b];
    float a[16], mx = -1e30f;
#pragma unroll
    for (int n = 0; n < 16; n++){
        a[n] = (n >= num) ? -1e9f : sc[n];
        mx = fmaxf(mx, a[n]);
    }
    float ssum = 0.f;
#pragma unroll
    for (int n = 0; n < 16; n++){ a[n] = expf(a[n]-mx); ssum += a[n]; }
    float inv = 1.f/ssum;
    float ctx = 0.f;
#pragma unroll
    for (int n = 0; n < 16; n++)
        ctx += a[n] * g_Vb[(size_t)(b*16+n)*HIz + h*64 + d];
    g_ctx[b*HIz + h*64 + d] = ctx*inv;
}

// --------------------------- first LSTM step -----------------------------
__global__ void k_step0(){
    int i = blockIdx.x*blockDim.x + threadIdx.x;
    if (i < Bz*Gz){
        int b = i >> 10, j = i & 1023;
        const float* g0 = g_g0 + (size_t)b*G4z;
        float gi = g0[j], gg = g0[j+2*Gz], go = g0[j+3*Gz];
        float c = sigf(gi)*tanhf(gg);
        float h = sigf(go)*tanhf(c);
        g_c[i] = c;
        bf16 hh = __float2bfloat16(h);
        g_H_hi[i] = hh;
        g_H_lo[i] = __float2bfloat16(h - __bfloat162float(hh));
    }
}

// ----------------- fused recurrence step (MMA + LSTM cell) ---------------
#define SLD 72
__global__ void __launch_bounds__(128, 1) k_step(int s){
    __shared__ bf16 sA[2][32*SLD];
    __shared__ bf16 sB[2][64*SLD];
    __shared__ float sG[4][32][16];
    const int tid = threadIdx.x, warp = tid >> 5, lane = tid & 31;
    const int nb = blockIdx.x;
    const bf16* hHi = g_H_hi + (size_t)s*Bz*Gz;
    const bf16* hLo = g_H_lo + (size_t)s*Bz*Gz;
    bf16* oHi = g_H_hi + (size_t)(s+1)*Bz*Gz;
    bf16* oLo = g_H_lo + (size_t)(s+1)*Bz*Gz;
    const float* Xg = g_Xg + (size_t)s*Bz*G4z;

    float acc[2][2][4];
#pragma unroll
    for (int a=0;a<2;a++)
#pragma unroll
    for (int b=0;b<2;b++)
#pragma unroll
    for (int c=0;c<4;c++) acc[a][b][c]=0.f;

    for (int kk = 0; kk < Gz; kk += 64){
#pragma unroll
        for (int i = 0; i < 2; i++){
            int u = tid + i*128;
            int r = u >> 3, c = (u & 7)*8;
            *(uint4*)&sA[0][r*SLD+c] = *(const uint4*)(hHi + (size_t)r*Gz + kk + c);
            *(uint4*)&sA[1][r*SLD+c] = *(const uint4*)(hLo + (size_t)r*Gz + kk + c);
        }
#pragma unroll
        for (int i = 0; i < 4; i++){
            int u = tid + i*128;
            int r = u >> 3, c = (u & 7)*8;
            int g = (r >> 4)*Gz + nb*16 + (r & 15);
            *(uint4*)&sB[0][r*SLD+c] = *(const uint4*)(g_Whh_hi + (size_t)g*Gz + kk + c);
            *(uint4*)&sB[1][r*SLD+c] = *(const uint4*)(g_Whh_lo + (size_t)g*Gz + kk + c);
        }
        __syncthreads();
#pragma unroll
        for (int ks = 0; ks < 64; ks += 16){
            uint32_t ah[2][4], al[2][4], bh[4], bl[4];
#pragma unroll
            for (int mi = 0; mi < 2; mi++){
                int row = mi*16 + (lane & 15);
                int kc  = ks + (lane >> 4)*8;
                ldsmx4(ah[mi], &sA[0][row*SLD + kc]);
                ldsmx4(al[mi], &sA[1][row*SLD + kc]);
            }
            {
                int j = lane >> 3;
                int row = warp*16 + ((j >> 1)*8) + (lane & 7);
                int kc  = ks + (j & 1)*8;
                ldsmx4(bh, &sB[0][row*SLD + kc]);
                ldsmx4(bl, &sB[1][row*SLD + kc]);
            }
#pragma unroll
            for (int mi = 0; mi < 2; mi++)
#pragma unroll
                for (int nj = 0; nj < 2; nj++){
                    mma16816(acc[mi][nj], ah[mi], &bh[nj*2]);
                    mma16816(acc[mi][nj], ah[mi], &bl[nj*2]);
                    mma16816(acc[mi][nj], al[mi], &bh[nj*2]);
                }
        }
        __syncthreads();
    }
#pragma unroll
    for (int mi = 0; mi < 2; mi++)
#pragma unroll
    for (int nj = 0; nj < 2; nj++)
#pragma unroll
    for (int h = 0; h < 2; h++){
        int b  = mi*16 + (lane >> 2) + h*8;
        int jl = nj*8 + (lane & 3)*2;
        sG[warp][b][jl]   = acc[mi][nj][h*2];
        sG[warp][b][jl+1] = acc[mi][nj][h*2+1];
    }
    __syncthreads();
    for (int e = tid; e < 512; e += 128){
        int b = e >> 4, jl = e & 15;
        int col = nb*16 + jl;
        const float* xg = Xg + (size_t)b*G4z;
        float gi = sG[0][b][jl] + xg[col];
        float gf = sG[1][b][jl] + xg[col +   Gz];
        float gg = sG[2][b][jl] + xg[col + 2*Gz];
        float go = sG[3][b][jl] + xg[col + 3*Gz];
        float c = sigf(gf)*g_c[b*Gz+col] + sigf(gi)*tanhf(gg);
        float h = sigf(go)*tanhf(c);
        g_c[b*Gz+col] = c;
        bf16 hh = __float2bfloat16(h);
        oHi[b*Gz+col] = hh;
        oLo[b*Gz+col] = __float2bfloat16(h - __bfloat162float(hh));
    }
}

// ------ pipelined split-bf16 GEMM:  D = A(hi+lo) @ B(hi+lo)^T + bias -----
// 128x128 tile, BK=32, 3-stage cp.async pipeline, 8 warps (2x4),
// warp tile 64x32, 3 MMA terms (AhBh + AhBl + AlBh).
// mode 0: out[m*N+n];  mode 1 (logits): m = t*32+b -> out[(b*127+t)*N + n]
#define LDT   40
#define MATB  (128*LDT*2)      /* 10240 B per 128x32 bf16 matrix */
#define STGB  (4*MATB)         /* Ahi,Alo,Bhi,Blo per stage       */
#define NSTG  3
#define GEMM_SMEM (NSTG*STGB)  /* 122880 B */

__global__ void __launch_bounds__(256, 1) k_gemm3p(
    const bf16* __restrict__ Ahi, const bf16* __restrict__ Alo,
    const bf16* __restrict__ Bhi, const bf16* __restrict__ Blo,
    const float* __restrict__ bias, float* __restrict__ out,
    int M, int N, int K, int mode)
{
    extern __shared__ char smem[];
    const uint32_t sb = smem_u32(smem);
    const int tid = threadIdx.x, warp = tid >> 5, lane = tid & 31;
    const int m0 = blockIdx.x*128, n0 = blockIdx.y*128;
    const int wm = (warp >> 2)*64, wn = (warp & 3)*32;
    const int NC = K >> 5;

    float acc[4][4][4];
#pragma unroll
    for (int a=0;a<4;a++)
#pragma unroll
    for (int b=0;b<4;b++)
#pragma unroll
    for (int c=0;c<4;c++) acc[a][b][c]=0.f;

    // thread's fixed load slot: 512 16B-chunks per matrix / 256 threads = 2
    // slot u = tid + i*256 -> row u>>2, col (u&3)*8 elements
    auto load_stage = [&](int chunk, int buf){
        const int kk = chunk << 5;
        const uint32_t s0 = sb + buf*STGB;
#pragma unroll
        for (int i = 0; i < 2; i++){
            int u = tid + i*256;
            int r = u >> 2, c = (u & 3)*8;
            uint32_t so = (uint32_t)((r*LDT + c)*2);
            int gr = m0 + r;
            uint32_t pv = (gr < M) ? 16u : 0u;
            int grc = gr < M ? gr : (M-1);
            CP_ASYNC16P(s0 + so,          Ahi + (size_t)grc*K + kk + c, pv);
            CP_ASYNC16P(s0 + MATB + so,   Alo + (size_t)grc*K + kk + c, pv);
            int gn = n0 + r;               // B rows always in-bounds
            CP_ASYNC16(s0 + 2*MATB + so,  Bhi + (size_t)gn*K + kk + c);
            CP_ASYNC16(s0 + 3*MATB + so,  Blo + (size_t)gn*K + kk + c);
        }
    };

    // preload NSTG-1 stages
    load_stage(0, 0); CP_COMMIT();
    if (NC > 1){ load_stage(1, 1); } CP_COMMIT();

    for (int c = 0; c < NC; c++){
        asm volatile("cp.async.wait_group 1;" ::: "memory");
        __syncthreads();
        if (c + 2 < NC) load_stage(c + 2, (c + 2) % NSTG);
        CP_COMMIT();

        const int buf = c % NSTG;
        const bf16* pA0 = (const bf16*)(smem + buf*STGB);
        const bf16* pA1 = (const bf16*)(smem + buf*STGB + MATB);
        const bf16* pB0 = (const bf16*)(smem + buf*STGB + 2*MATB);
        const bf16* pB1 = (const bf16*)(smem + buf*STGB + 3*MATB);
#pragma unroll
        for (int ks = 0; ks < 32; ks += 16){
            uint32_t ah[4][4], al[4][4], bh[2][4], bl[2][4];
#pragma unroll
            for (int mi = 0; mi < 4; mi++){
                int row = wm + mi*16 + (lane & 15);
                int kc  = ks + (lane >> 4)*8;
                ldsmx4(ah[mi], pA0 + row*LDT + kc);
                ldsmx4(al[mi], pA1 + row*LDT + kc);
            }
#pragma unroll
            for (int ni = 0; ni < 2; ni++){
                int j = lane >> 3;
                int row = wn + ni*16 + ((j >> 1)*8) + (lane & 7);
                int kc  = ks + (j & 1)*8;
                ldsmx4(bh[ni], pB0 + row*LDT + kc);
                ldsmx4(bl[ni], pB1 + row*LDT + kc);
            }
#pragma unroll
            for (int mi = 0; mi < 4; mi++)
#pragma unroll
                for (int nj = 0; nj < 4; nj++){
                    const uint32_t* fh = &bh[nj >> 1][(nj & 1)*2];
                    const uint32_t* fl = &bl[nj >> 1][(nj & 1)*2];
                    mma16816(acc[mi][nj], ah[mi], fh);
                    mma16816(acc[mi][nj], ah[mi], fl);
                    mma16816(acc[mi][nj], al[mi], fh);
                }
        }
    }

    // epilogue
#pragma unroll
    for (int mi = 0; mi < 4; mi++)
#pragma unroll
    for (int nj = 0; nj < 4; nj++){
        int n = n0 + wn + nj*8 + (lane & 3)*2;
        float b0 = bias[n], b1 = bias[n+1];
#pragma unroll
        for (int h = 0; h < 2; h++){
            int m = m0 + wm + mi*16 + (lane >> 2) + h*8;
            if (m < M){
                size_t off;
                if (mode == 1){
                    int t = m >> 5, b = m & 31;
                    off = ((size_t)b*Tz + t)*(size_t)N + n;
                } else {
                    off = (size_t)m*N + n;
                }
                out[off]   = acc[mi][nj][h*2]   + b0;
                out[off+1] = acc[mi][nj][h*2+1] + b1;
            }
        }
    }
}

// ------------------------------- tail ------------------------------------
__global__ void k_tail(const int* __restrict__ sent, const int* __restrict__ slen,
                       float* __restrict__ out, long out_size){
    long base = (long)Bz*Tz*Vz;
    int i = blockIdx.x*blockDim.x + threadIdx.x;
    if (i < Bz*Sz && base + i < out_size)            out[base+i] = (float)sent[i];
    if (i < Bz && base + Bz*Sz + i < out_size)       out[base+Bz*Sz+i] = (float)slen[i];
}

// ------------------------------ host side --------------------------------
extern "C" void kernel_launch(void* const* d_in, const int* in_sizes, int n_in,
                              void* d_out, int out_size) {
    const float* ent   = (const float*)d_in[0];
    const float* neigh = (const float*)d_in[1];
    const int*   nnum  = (const int*)  d_in[2];
    const float* img   = (const float*)d_in[3];
    const int*   sent  = (const int*)  d_in[4];
    const int*   slen  = (const int*)  d_in[5];
    const float* emb   = (const float*)d_in[6];
    const float* W_ih  = (const float*)d_in[7];
    const float* W_hh  = (const float*)d_in[8];
    const float* b_ih  = (const float*)d_in[9];
    const float* b_hh  = (const float*)d_in[10];
    const float* W_img = (const float*)d_in[11];
    const float* b_img = (const float*)d_in[12];
    const float* W_out = (const float*)d_in[13];
    const float* b_out = (const float*)d_in[14];
    const float* Wq = (const float*)d_in[15]; const float* bq = (const float*)d_in[16];
    const float* Wk = (const float*)d_in[17]; const float* bk = (const float*)d_in[18];
    const float* Wv = (const float*)d_in[19]; const float* bv = (const float*)d_in[20];
    const float* Wo = (const float*)d_in[21]; const float* bo = (const float*)d_in[22];
    float* out = (float*)d_out;

    void *pWout_hi, *pWout_lo, *pWih_hi, *pWih_lo, *pWhh_hi, *pWhh_lo;
    void *pXhi, *pXlo, *pXg, *pHhi, *pHlo, *pBsum;
    void *pQ, *pKb, *pVb, *pCtx, *pAtt, *pFf, *pIe, *pG0;
    cudaGetSymbolAddress(&pWout_hi, g_Wout_hi); cudaGetSymbolAddress(&pWout_lo, g_Wout_lo);
    cudaGetSymbolAddress(&pWih_hi,  g_Wih_hi);  cudaGetSymbolAddress(&pWih_lo,  g_Wih_lo);
    cudaGetSymbolAddress(&pWhh_hi,  g_Whh_hi);  cudaGetSymbolAddress(&pWhh_lo,  g_Whh_lo);
    cudaGetSymbolAddress(&pXhi, g_X_hi); cudaGetSymbolAddress(&pXlo, g_X_lo);
    cudaGetSymbolAddress(&pXg,  g_Xg);   cudaGetSymbolAddress(&pBsum, g_bsum);
    cudaGetSymbolAddress(&pHhi, g_H_hi); cudaGetSymbolAddress(&pHlo, g_H_lo);
    cudaGetSymbolAddress(&pQ, g_Q); cudaGetSymbolAddress(&pKb, g_Kb);
    cudaGetSymbolAddress(&pVb, g_Vb); cudaGetSymbolAddress(&pCtx, g_ctx);
    cudaGetSymbolAddress(&pAtt, g_att); cudaGetSymbolAddress(&pFf, g_ff);
    cudaGetSymbolAddress(&pIe, g_ie); cudaGetSymbolAddress(&pG0, g_g0);

    cudaFuncSetAttribute(k_gemm3p, cudaFuncAttributeMaxDynamicSharedMemorySize, GEMM_SMEM);

    // ---- prep: split weights to bf16 hi/lo, gather+split embeddings ----
    {
        int n = Vz*Gz;
        k_split<<<(n+255)/256, 256>>>(W_out, (bf16*)pWout_hi, (bf16*)pWout_lo, n);
        n = G4z*Ez;
        k_split<<<(n+255)/256, 256>>>(W_ih, (bf16*)pWih_hi, (bf16*)pWih_lo, n);
        n = G4z*Gz;
        k_split<<<(n+255)/256, 256>>>(W_hh, (bf16*)pWhh_hi, (bf16*)pWhh_lo, n);
        k_bsum<<<(G4z+255)/256, 256>>>(b_ih, b_hh);
        n = MR*Ez;
        k_xgather<<<(n+255)/256, 256>>>(emb, sent);
    }

    // ---- prologue: MHA + img_embed + first LSTM step ----
    k_small<<<(Bz*HIz*32+255)/256, 256>>>(ent, Wq, bq, (float*)pQ, Bz, HIz, HIz, 0);
    k_small<<<(Bz*16*HIz*32+255)/256, 256>>>(neigh, Wk, bk, (float*)pKb, Bz*16, HIz, HIz, 0);
    k_small<<<(Bz*16*HIz*32+255)/256, 256>>>(neigh, Wv, bv, (float*)pVb, Bz*16, HIz, HIz, 0);
    k_attn<<<Bz*8, 64>>>(nnum);
    k_small<<<(Bz*HIz*32+255)/256, 256>>>((const float*)pCtx, Wo, bo, (float*)pAtt, Bz, HIz, HIz, 0);
    k_ff<<<(Bz*HIz+255)/256, 256>>>(ent, img);
    k_small<<<(Bz*HIz*32+255)/256, 256>>>((const float*)pFf, W_img, b_img, (float*)pIe, Bz, HIz, 3*HIz, 1);
    k_small<<<(Bz*G4z*32+255)/256, 256>>>((const float*)pIe, W_ih, (const float*)pBsum, (float*)pG0, Bz, G4z, Ez, 0);
    k_step0<<<(Bz*Gz+255)/256, 256>>>();

    // ---- Xg = X @ W_ih^T + bsum for all 127 steps (one pipelined GEMM) ----
    {
        dim3 grid((MR+127)/128, G4z/128);
        k_gemm3p<<<grid, 256, GEMM_SMEM>>>((const bf16*)pXhi, (const bf16*)pXlo,
                               (const bf16*)pWih_hi, (const bf16*)pWih_lo,
                               (const float*)pBsum, (float*)pXg,
                               MR, G4z, Ez, 0);
    }

    // ---- recurrence: 127 fused steps ----
    for (int s = 0; s < Tz; s++)
        k_step<<<64, 128>>>(s);

    // ---- logits: [4064,1024] x [1024,32000] pipelined, remap [B,T,V] ----
    {
        dim3 grid((MR+127)/128, Vz/128);   // 32 x 250, m fastest for L2 reuse
        k_gemm3p<<<grid, 256, GEMM_SMEM>>>(
            (const bf16*)pHhi + Bz*Gz, (const bf16*)pHlo + Bz*Gz,
            (const bf16*)pWout_hi, (const bf16*)pWout_lo,
            b_out, out, MR, Vz, Gz, 1);
    }

    // ---- tuple tail (target_sent, target_sent_len) if harness expects it ----
    if ((long)out_size > (long)Bz*Tz*Vz)
        k_tail<<<(Bz*Sz+255)/256, 256>>>(sent, slen, out, (long)out_size);
}

// round 12
// speedup vs baseline: 1.5509x; 1.3942x over previous
#include <cuda_runtime.h>
#include <cuda_bf16.h>
#include <cuda_fp16.h>
#include <cstdint>

typedef __nv_bfloat16 bf16;

#define Bz   32
#define Sz   128
#define Tz   127
#define Vz   32000
#define Ez   512
#define Gz   1024
#define HIz  512
#define G4z  4096
#define MR   4064   /* Tz*Bz */

// ------------------------- static device scratch -------------------------
__device__ __half g_Woutf[(size_t)Vz*Gz];           // fp16 hi of W_out (lo dropped)
__device__ bf16  g_Wih_hi[(size_t)G4z*Ez];
__device__ bf16  g_Wih_lo[(size_t)G4z*Ez];
__device__ bf16  g_Whh_hi[(size_t)G4z*Gz];
__device__ bf16  g_Whh_lo[(size_t)G4z*Gz];
__device__ bf16  g_H_hi[(size_t)(Tz+2)*Bz*Gz];      // bf16 h for recurrence
__device__ bf16  g_H_lo[(size_t)(Tz+2)*Bz*Gz];
__device__ __half g_Hf_hi[(size_t)(Tz+2)*Bz*Gz];    // fp16 h for logits
__device__ __half g_Hf_lo[(size_t)(Tz+2)*Bz*Gz];
__device__ bf16  g_X_hi[(size_t)MR*Ez];
__device__ bf16  g_X_lo[(size_t)MR*Ez];
__device__ float g_Xg[(size_t)MR*G4z];
__device__ float g_c[Bz*Gz];
__device__ float g_Q[Bz*HIz];
__device__ float g_Kb[Bz*16*HIz];
__device__ float g_Vb[Bz*16*HIz];
__device__ float g_ctx[Bz*HIz];
__device__ float g_att[Bz*HIz];
__device__ float g_ff[Bz*3*HIz];
__device__ float g_ie[Bz*Ez];
__device__ float g_g0[Bz*G4z];
__device__ float g_bsum[G4z];
// prologue split buffers (bf16 hi/lo)
__device__ bf16 g_ent_h[Bz*HIz],   g_ent_l[Bz*HIz];
__device__ bf16 g_nei_h[Bz*16*HIz],g_nei_l[Bz*16*HIz];
__device__ bf16 g_ctx_h[Bz*HIz],   g_ctx_l[Bz*HIz];
__device__ bf16 g_ffs_h[Bz*3*HIz], g_ffs_l[Bz*3*HIz];
__device__ bf16 g_ie_h[Bz*Ez],     g_ie_l[Bz*Ez];
__device__ bf16 g_Wq_h[HIz*HIz],   g_Wq_l[HIz*HIz];
__device__ bf16 g_Wk_h[HIz*HIz],   g_Wk_l[HIz*HIz];
__device__ bf16 g_Wv_h[HIz*HIz],   g_Wv_l[HIz*HIz];
__device__ bf16 g_Wo_h[HIz*HIz],   g_Wo_l[HIz*HIz];
__device__ bf16 g_Wim_h[Ez*3*HIz], g_Wim_l[Ez*3*HIz];

// ------------------------------ helpers ----------------------------------
__device__ __forceinline__ float sigf(float x){ return 1.0f/(1.0f+expf(-x)); }

__device__ __forceinline__ uint32_t smem_u32(const void* p){
    return (uint32_t)__cvta_generic_to_shared(p);
}
__device__ __forceinline__ void ldsmx4(uint32_t* r, const void* p){
    uint32_t a = smem_u32(p);
    asm volatile("ldmatrix.sync.aligned.m8n8.x4.shared.b16 {%0,%1,%2,%3},[%4];\n"
                 : "=r"(r[0]),"=r"(r[1]),"=r"(r[2]),"=r"(r[3]) : "r"(a));
}
__device__ __forceinline__ void ldsmx2(uint32_t* r, const void* p){
    uint32_t a = smem_u32(p);
    asm volatile("ldmatrix.sync.aligned.m8n8.x2.shared.b16 {%0,%1},[%2];\n"
                 : "=r"(r[0]),"=r"(r[1]) : "r"(a));
}
__device__ __forceinline__ void mma_bf(float* d, const uint32_t* a, const uint32_t* b){
    asm volatile("mma.sync.aligned.m16n8k16.row.col.f32.bf16.bf16.f32 "
                 "{%0,%1,%2,%3},{%4,%5,%6,%7},{%8,%9},{%0,%1,%2,%3};\n"
                 : "+f"(d[0]),"+f"(d[1]),"+f"(d[2]),"+f"(d[3])
                 : "r"(a[0]),"r"(a[1]),"r"(a[2]),"r"(a[3]),
                   "r"(b[0]),"r"(b[1]));
}
__device__ __forceinline__ void mma_fp(float* d, const uint32_t* a, const uint32_t* b){
    asm volatile("mma.sync.aligned.m16n8k16.row.col.f32.f16.f16.f32 "
                 "{%0,%1,%2,%3},{%4,%5,%6,%7},{%8,%9},{%0,%1,%2,%3};\n"
                 : "+f"(d[0]),"+f"(d[1]),"+f"(d[2]),"+f"(d[3])
                 : "r"(a[0]),"r"(a[1]),"r"(a[2]),"r"(a[3]),
                   "r"(b[0]),"r"(b[1]));
}
#define CP_ASYNC16P(dst, src, pv) \
    asm volatile("cp.async.cg.shared.global [%0], [%1], 16, %2;" \
                 :: "r"(dst), "l"(src), "r"(pv))
#define CP_ASYNC16(dst, src) \
    asm volatile("cp.async.cg.shared.global [%0], [%1], 16;" :: "r"(dst), "l"(src))
#define CP_COMMIT()  asm volatile("cp.async.commit_group;" ::: "memory")

// --------------------------- prep kernels --------------------------------
__global__ void k_split(const float* __restrict__ src, bf16* __restrict__ hi,
                        bf16* __restrict__ lo, int n){
    int i = blockIdx.x*blockDim.x + threadIdx.x;
    if (i < n){
        float x = src[i];
        bf16 h = __float2bfloat16(x);
        hi[i] = h;
        lo[i] = __float2bfloat16(x - __bfloat162float(h));
    }
}
__global__ void k_half(const float* __restrict__ src, __half* __restrict__ dst, int n){
    int i = blockIdx.x*blockDim.x + threadIdx.x;
    if (i < n) dst[i] = __float2half(src[i]);
}
__global__ void k_bsum(const float* __restrict__ a, const float* __restrict__ b){
    int i = blockIdx.x*blockDim.x + threadIdx.x;
    if (i < G4z) g_bsum[i] = a[i] + b[i];
}
__global__ void k_xgather(const float* __restrict__ emb, const int* __restrict__ sent){
    int i = blockIdx.x*blockDim.x + threadIdx.x;
    if (i < MR*Ez){
        int r = i >> 9, col = i & 511;
        int t = r >> 5, b = r & 31;
        int idx = sent[b*Sz + t];
        float v = emb[(size_t)idx*Ez + col];
        bf16 h = __float2bfloat16(v);
        g_X_hi[i] = h;
        g_X_lo[i] = __float2bfloat16(v - __bfloat162float(h));
    }
}
__global__ void k_ff(const float* __restrict__ ent, const float* __restrict__ img){
    int i = blockIdx.x*blockDim.x + threadIdx.x;
    if (i < Bz*HIz){
        int b = i >> 9, j = i & 511;
        float* row = g_ff + (size_t)b*3*HIz;
        row[j]          = ent[i];
        row[HIz + j]    = g_att[i];
        row[2*HIz + j]  = img[i];
    }
}

// ------------------------------ attention --------------------------------
__global__ void k_attn(const int* __restrict__ nnum){
    int bh = blockIdx.x;
    int b = bh >> 3, h = bh & 7;
    int d = threadIdx.x;                    // 64 threads
    __shared__ float red[64];
    __shared__ float sc[16];
    float q = g_Q[b*HIz + h*64 + d];
    for (int n = 0; n < 16; n++){
        red[d] = q * g_Kb[(size_t)(b*16+n)*HIz + h*64 + d];
        __syncthreads();
        for (int o = 32; o; o >>= 1){
            if (d < o) red[d] += red[d+o];
            __syncthreads();
        }
        if (d == 0) sc[n] = red[0]*0.125f;
        __syncthreads();
    }
    int num = nnum[b];
    float a[16], mx = -1e30f;
#pragma unroll
    for (int n = 0; n < 16; n++){
        a[n] = (n >= num) ? -1e9f : sc[n];
        mx = fmaxf(mx, a[n]);
    }
    float ssum = 0.f;
#pragma unroll
    for (int n = 0; n < 16; n++){ a[n] = expf(a[n]-mx); ssum += a[n]; }
    float inv = 1.f/ssum;
    float ctx = 0.f;
#pragma unroll
    for (int n = 0; n < 16; n++)
        ctx += a[n] * g_Vb[(size_t)(b*16+n)*HIz + h*64 + d];
    g_ctx[b*HIz + h*64 + d] = ctx*inv;
}

// --------------------------- first LSTM step -----------------------------
__global__ void k_step0(){
    int i = blockIdx.x*blockDim.x + threadIdx.x;
    if (i < Bz*Gz){
        int b = i >> 10, j = i & 1023;
        const float* g0 = g_g0 + (size_t)b*G4z;
        float gi = g0[j], gg = g0[j+2*Gz], go = g0[j+3*Gz];
        float c = sigf(gi)*tanhf(gg);
        float h = sigf(go)*tanhf(c);
        g_c[i] = c;
        bf16 hh = __float2bfloat16(h);
        g_H_hi[i] = hh;
        g_H_lo[i] = __float2bfloat16(h - __bfloat162float(hh));
    }
}

// ---- fused recurrence step: 128 blocks x 128 thr, cp.async 3-stage ------
// Block nb owns gate cols {nb*8..+7} across all 4 quadrants (warp=quadrant).
#define SLD2 72
#define STEP_MAT (32*SLD2*2)     /* 4608 B per 32x64 bf16 matrix */
#define STEP_STG (4*STEP_MAT)    /* Ahi,Alo,Bhi,Blo = 18432 */
#define STEP_SMEM (3*STEP_STG)   /* 55296 */
__global__ void __launch_bounds__(128, 1) k_step(int s){
    extern __shared__ char dsm[];
    __shared__ float sG[4][32][8];
    const uint32_t sb = smem_u32(dsm);
    const int tid = threadIdx.x, warp = tid >> 5, lane = tid & 31;
    const int nb = blockIdx.x, c0 = nb*8;
    const bf16* hHi = g_H_hi + (size_t)s*Bz*Gz;
    const bf16* hLo = g_H_lo + (size_t)s*Bz*Gz;

    float acc[2][4];
#pragma unroll
    for (int a=0;a<2;a++)
#pragma unroll
    for (int c=0;c<4;c++) acc[a][c]=0.f;

    auto load_stage = [&](int ch, int buf){
        const int kk = ch*64;
        const uint32_t s0 = sb + buf*STEP_STG;
#pragma unroll
        for (int i = 0; i < 2; i++){
            int u = tid + i*128;
            int r = u >> 3, c = (u & 7)*8;
            uint32_t so = (uint32_t)((r*SLD2 + c)*2);
            CP_ASYNC16(s0 + so,              hHi + (size_t)r*Gz + kk + c);
            CP_ASYNC16(s0 + STEP_MAT + so,   hLo + (size_t)r*Gz + kk + c);
            int g = (r >> 3)*Gz + c0 + (r & 7);
            CP_ASYNC16(s0 + 2*STEP_MAT + so, g_Whh_hi + (size_t)g*Gz + kk + c);
            CP_ASYNC16(s0 + 3*STEP_MAT + so, g_Whh_lo + (size_t)g*Gz + kk + c);
        }
    };
    load_stage(0, 0); CP_COMMIT();
    load_stage(1, 1); CP_COMMIT();

    for (int ch = 0; ch < 16; ch++){
        asm volatile("cp.async.wait_group 1;" ::: "memory");
        __syncthreads();
        if (ch + 2 < 16) load_stage(ch + 2, (ch + 2) % 3);
        CP_COMMIT();
        const char* st = dsm + (ch % 3)*STEP_STG;
        const bf16* pA0 = (const bf16*)(st);
        const bf16* pA1 = (const bf16*)(st + STEP_MAT);
        const bf16* pB0 = (const bf16*)(st + 2*STEP_MAT);
        const bf16* pB1 = (const bf16*)(st + 3*STEP_MAT);
#pragma unroll
        for (int ks = 0; ks < 64; ks += 16){
            uint32_t ah[2][4], al[2][4], bh[2], bl[2];
#pragma unroll
            for (int mi = 0; mi < 2; mi++){
                int row = mi*16 + (lane & 15);
                int kc  = ks + (lane >> 4)*8;
                ldsmx4(ah[mi], pA0 + row*SLD2 + kc);
                ldsmx4(al[mi], pA1 + row*SLD2 + kc);
            }
            {
                int l = lane & 15;
                int row = warp*8 + (l & 7);
                int kc  = ks + ((l >> 3) & 1)*8;
                ldsmx2(bh, pB0 + row*SLD2 + kc);
                ldsmx2(bl, pB1 + row*SLD2 + kc);
            }
#pragma unroll
            for (int mi = 0; mi < 2; mi++){
                mma_bf(acc[mi], ah[mi], bh);
                mma_bf(acc[mi], ah[mi], bl);
                mma_bf(acc[mi], al[mi], bh);
            }
        }
    }
    // scatter: warp q holds quadrant q for (b, jl)
#pragma unroll
    for (int mi = 0; mi < 2; mi++)
#pragma unroll
    for (int h = 0; h < 2; h++){
        int b  = mi*16 + (lane >> 2) + h*8;
        int jl = (lane & 3)*2;
        sG[warp][b][jl]   = acc[mi][h*2];
        sG[warp][b][jl+1] = acc[mi][h*2+1];
    }
    __syncthreads();
    // LSTM cell update: 32x8 elements
    bf16* oHi = g_H_hi + (size_t)(s+1)*Bz*Gz;
    bf16* oLo = g_H_lo + (size_t)(s+1)*Bz*Gz;
    __half* fHi = g_Hf_hi + (size_t)(s+1)*Bz*Gz;
    __half* fLo = g_Hf_lo + (size_t)(s+1)*Bz*Gz;
    const float* Xg = g_Xg + (size_t)s*Bz*G4z;
    for (int e = tid; e < 256; e += 128){
        int b = e >> 3, jl = e & 7;
        int col = c0 + jl;
        const float* xg = Xg + (size_t)b*G4z;
        float gi = sG[0][b][jl] + xg[col];
        float gf = sG[1][b][jl] + xg[col +   Gz];
        float gg = sG[2][b][jl] + xg[col + 2*Gz];
        float go = sG[3][b][jl] + xg[col + 3*Gz];
        float c = sigf(gf)*g_c[b*Gz+col] + sigf(gi)*tanhf(gg);
        float h = sigf(go)*tanhf(c);
        g_c[b*Gz+col] = c;
        bf16 hb = __float2bfloat16(h);
        oHi[b*Gz+col] = hb;
        oLo[b*Gz+col] = __float2bfloat16(h - __bfloat162float(hb));
        __half hf = __float2half(h);
        fHi[b*Gz+col] = hf;
        fLo[b*Gz+col] = __float2half(h - __half2float(hf));
    }
}

// ------ pipelined split-bf16 3-term GEMM (Xg + prologue), act 0/1=tanh ---
#define LDT   40
#define MATB  (128*LDT*2)
#define STGB  (4*MATB)
#define GEMM_SMEM (3*STGB)       /* 122880 */
__global__ void __launch_bounds__(256, 1) k_gemm3p(
    const bf16* __restrict__ Ahi, const bf16* __restrict__ Alo,
    const bf16* __restrict__ Bhi, const bf16* __restrict__ Blo,
    const float* __restrict__ bias, float* __restrict__ out,
    int M, int N, int K, int act)
{
    extern __shared__ char smem[];
    const uint32_t sb = smem_u32(smem);
    const int tid = threadIdx.x, warp = tid >> 5, lane = tid & 31;
    const int m0 = blockIdx.x*128, n0 = blockIdx.y*128;
    const int wm = (warp >> 2)*64, wn = (warp & 3)*32;
    const int NC = K >> 5;

    float acc[4][4][4];
#pragma unroll
    for (int a=0;a<4;a++)
#pragma unroll
    for (int b=0;b<4;b++)
#pragma unroll
    for (int c=0;c<4;c++) acc[a][b][c]=0.f;

    auto load_stage = [&](int chunk, int buf){
        const int kk = chunk << 5;
        const uint32_t s0 = sb + buf*STGB;
#pragma unroll
        for (int i = 0; i < 2; i++){
            int u = tid + i*256;
            int r = u >> 2, c = (u & 3)*8;
            uint32_t so = (uint32_t)((r*LDT + c)*2);
            int gr = m0 + r;
            uint32_t pv = (gr < M) ? 16u : 0u;
            int grc = gr < M ? gr : (M-1);
            CP_ASYNC16P(s0 + so,          Ahi + (size_t)grc*K + kk + c, pv);
            CP_ASYNC16P(s0 + MATB + so,   Alo + (size_t)grc*K + kk + c, pv);
            int gn = n0 + r;
            CP_ASYNC16(s0 + 2*MATB + so,  Bhi + (size_t)gn*K + kk + c);
            CP_ASYNC16(s0 + 3*MATB + so,  Blo + (size_t)gn*K + kk + c);
        }
    };
    load_stage(0, 0); CP_COMMIT();
    if (NC > 1){ load_stage(1, 1); } CP_COMMIT();

    for (int c = 0; c < NC; c++){
        asm volatile("cp.async.wait_group 1;" ::: "memory");
        __syncthreads();
        if (c + 2 < NC) load_stage(c + 2, (c + 2) % 3);
        CP_COMMIT();
        const char* st = smem + (c % 3)*STGB;
        const bf16* pA0 = (const bf16*)(st);
        const bf16* pA1 = (const bf16*)(st + MATB);
        const bf16* pB0 = (const bf16*)(st + 2*MATB);
        const bf16* pB1 = (const bf16*)(st + 3*MATB);
#pragma unroll
        for (int ks = 0; ks < 32; ks += 16){
            uint32_t ah[4][4], al[4][4], bh[2][4], bl[2][4];
#pragma unroll
            for (int mi = 0; mi < 4; mi++){
                int row = wm + mi*16 + (lane & 15);
                int kc  = ks + (lane >> 4)*8;
                ldsmx4(ah[mi], pA0 + row*LDT + kc);
                ldsmx4(al[mi], pA1 + row*LDT + kc);
            }
#pragma unroll
            for (int ni = 0; ni < 2; ni++){
                int j = lane >> 3;
                int row = wn + ni*16 + ((j >> 1)*8) + (lane & 7);
                int kc  = ks + (j & 1)*8;
                ldsmx4(bh[ni], pB0 + row*LDT + kc);
                ldsmx4(bl[ni], pB1 + row*LDT + kc);
            }
#pragma unroll
            for (int mi = 0; mi < 4; mi++)
#pragma unroll
                for (int nj = 0; nj < 4; nj++){
                    const uint32_t* fh = &bh[nj >> 1][(nj & 1)*2];
                    const uint32_t* fl = &bl[nj >> 1][(nj & 1)*2];
                    mma_bf(acc[mi][nj], ah[mi], fh);
                    mma_bf(acc[mi][nj], ah[mi], fl);
                    mma_bf(acc[mi][nj], al[mi], fh);
                }
        }
    }
#pragma unroll
    for (int mi = 0; mi < 4; mi++)
#pragma unroll
    for (int nj = 0; nj < 4; nj++){
        int n = n0 + wn + nj*8 + (lane & 3)*2;
        float b0 = bias[n], b1 = bias[n+1];
#pragma unroll
        for (int h = 0; h < 2; h++){
            int m = m0 + wm + mi*16 + (lane >> 2) + h*8;
            if (m < M){
                float v0 = acc[mi][nj][h*2]   + b0;
                float v1 = acc[mi][nj][h*2+1] + b1;
                if (act == 1){ v0 = tanhf(v0); v1 = tanhf(v1); }
                out[(size_t)m*N + n]   = v0;
                out[(size_t)m*N + n+1] = v1;
            }
        }
    }
}

// ---- logits: fp16 2-term pipelined GEMM, D = (Ah+Al) @ Bh^T + bias ------
// remap: row m = t*32+b  ->  out[(b*127+t)*Vz + n]
#define MATB2 (128*LDT*2)        /* 10240 */
#define STGB2 (3*MATB2)          /* Ah, Al, Bh */
#define LOG_SMEM (3*STGB2)       /* 92160 */
__global__ void __launch_bounds__(256, 1) k_logits16(
    const __half* __restrict__ Ahi, const __half* __restrict__ Alo,
    const __half* __restrict__ Bhi,
    const float* __restrict__ bias, float* __restrict__ out,
    int M, int N, int K)
{
    extern __shared__ char smem[];
    const uint32_t sb = smem_u32(smem);
    const int tid = threadIdx.x, warp = tid >> 5, lane = tid & 31;
    const int m0 = blockIdx.x*128, n0 = blockIdx.y*128;
    const int wm = (warp >> 2)*64, wn = (warp & 3)*32;
    const int NC = K >> 5;

    float acc[4][4][4];
#pragma unroll
    for (int a=0;a<4;a++)
#pragma unroll
    for (int b=0;b<4;b++)
#pragma unroll
    for (int c=0;c<4;c++) acc[a][b][c]=0.f;

    auto load_stage = [&](int chunk, int buf){
        const int kk = chunk << 5;
        const uint32_t s0 = sb + buf*STGB2;
#pragma unroll
        for (int i = 0; i < 2; i++){
            int u = tid + i*256;
            int r = u >> 2, c = (u & 3)*8;
            uint32_t so = (uint32_t)((r*LDT + c)*2);
            int gr = m0 + r;
            uint32_t pv = (gr < M) ? 16u : 0u;
            int grc = gr < M ? gr : (M-1);
            CP_ASYNC16P(s0 + so,          Ahi + (size_t)grc*K + kk + c, pv);
            CP_ASYNC16P(s0 + MATB2 + so,  Alo + (size_t)grc*K + kk + c, pv);
            int gn = n0 + r;
            CP_ASYNC16(s0 + 2*MATB2 + so, Bhi + (size_t)gn*K + kk + c);
        }
    };
    load_stage(0, 0); CP_COMMIT();
    load_stage(1, 1); CP_COMMIT();

    for (int c = 0; c < NC; c++){
        asm volatile("cp.async.wait_group 1;" ::: "memory");
        __syncthreads();
        if (c + 2 < NC) load_stage(c + 2, (c + 2) % 3);
        CP_COMMIT();
        const char* st = smem + (c % 3)*STGB2;
        const __half* pA0 = (const __half*)(st);
        const __half* pA1 = (const __half*)(st + MATB2);
        const __half* pB0 = (const __half*)(st + 2*MATB2);
#pragma unroll
        for (int ks = 0; ks < 32; ks += 16){
            uint32_t ah[4][4], al[4][4], bh[2][4];
#pragma unroll
            for (int mi = 0; mi < 4; mi++){
                int row = wm + mi*16 + (lane & 15);
                int kc  = ks + (lane >> 4)*8;
                ldsmx4(ah[mi], pA0 + row*LDT + kc);
                ldsmx4(al[mi], pA1 + row*LDT + kc);
            }
#pragma unroll
            for (int ni = 0; ni < 2; ni++){
                int j = lane >> 3;
                int row = wn + ni*16 + ((j >> 1)*8) + (lane & 7);
                int kc  = ks + (j & 1)*8;
                ldsmx4(bh[ni], pB0 + row*LDT + kc);
            }
#pragma unroll
            for (int mi = 0; mi < 4; mi++)
#pragma unroll
                for (int nj = 0; nj < 4; nj++){
                    const uint32_t* fh = &bh[nj >> 1][(nj & 1)*2];
                    mma_fp(acc[mi][nj], ah[mi], fh);
                    mma_fp(acc[mi][nj], al[mi], fh);
                }
        }
    }
#pragma unroll
    for (int mi = 0; mi < 4; mi++)
#pragma unroll
    for (int nj = 0; nj < 4; nj++){
        int n = n0 + wn + nj*8 + (lane & 3)*2;
        float b0 = bias[n], b1 = bias[n+1];
#pragma unroll
        for (int h = 0; h < 2; h++){
            int m = m0 + wm + mi*16 + (lane >> 2) + h*8;
            if (m < M){
                int t = m >> 5, b = m & 31;
                size_t off = ((size_t)b*Tz + t)*(size_t)N + n;
                out[off]   = acc[mi][nj][h*2]   + b0;
                out[off+1] = acc[mi][nj][h*2+1] + b1;
            }
        }
    }
}

// ------------------------------- tail ------------------------------------
__global__ void k_tail(const int* __restrict__ sent, const int* __restrict__ slen,
                       float* __restrict__ out, long out_size){
    long base = (long)Bz*Tz*Vz;
    int i = blockIdx.x*blockDim.x + threadIdx.x;
    if (i < Bz*Sz && base + i < out_size)            out[base+i] = (float)sent[i];
    if (i < Bz && base + Bz*Sz + i < out_size)       out[base+Bz*Sz+i] = (float)slen[i];
}

// ------------------------------ host side --------------------------------
static inline void* sym(const void* s){ void* p; cudaGetSymbolAddress(&p, s); return p; }

extern "C" void kernel_launch(void* const* d_in, const int* in_sizes, int n_in,
                              void* d_out, int out_size) {
    const float* ent   = (const float*)d_in[0];
    const float* neigh = (const float*)d_in[1];
    const int*   nnum  = (const int*)  d_in[2];
    const float* img   = (const float*)d_in[3];
    const int*   sent  = (const int*)  d_in[4];
    const int*   slen  = (const int*)  d_in[5];
    const float* emb   = (const float*)d_in[6];
    const float* W_ih  = (const float*)d_in[7];
    const float* W_hh  = (const float*)d_in[8];
    const float* b_ih  = (const float*)d_in[9];
    const float* b_hh  = (const float*)d_in[10];
    const float* W_img = (const float*)d_in[11];
    const float* b_img = (const float*)d_in[12];
    const float* W_out = (const float*)d_in[13];
    const float* b_out = (const float*)d_in[14];
    const float* Wq = (const float*)d_in[15]; const float* bq = (const float*)d_in[16];
    const float* Wk = (const float*)d_in[17]; const float* bk = (const float*)d_in[18];
    const float* Wv = (const float*)d_in[19]; const float* bv = (const float*)d_in[20];
    const float* Wo = (const float*)d_in[21]; const float* bo = (const float*)d_in[22];
    float* out = (float*)d_out;

    void *pWoutf = sym(g_Woutf);
    void *pWih_h = sym(g_Wih_hi), *pWih_l = sym(g_Wih_lo);
    void *pWhh_h = sym(g_Whh_hi), *pWhh_l = sym(g_Whh_lo);
    void *pHf_h = sym(g_Hf_hi), *pHf_l = sym(g_Hf_lo);
    void *pXh = sym(g_X_hi), *pXl = sym(g_X_lo);
    void *pXg = sym(g_Xg), *pBsum = sym(g_bsum);
    void *pQ = sym(g_Q), *pKb = sym(g_Kb), *pVb = sym(g_Vb);
    void *pCtx = sym(g_ctx), *pAtt = sym(g_att), *pFf = sym(g_ff);
    void *pIe = sym(g_ie), *pG0 = sym(g_g0);
    void *pEnt_h = sym(g_ent_h), *pEnt_l = sym(g_ent_l);
    void *pNei_h = sym(g_nei_h), *pNei_l = sym(g_nei_l);
    void *pCtx_h = sym(g_ctx_h), *pCtx_l = sym(g_ctx_l);
    void *pFfs_h = sym(g_ffs_h), *pFfs_l = sym(g_ffs_l);
    void *pIe_h = sym(g_ie_h), *pIe_l = sym(g_ie_l);
    void *pWq_h = sym(g_Wq_h), *pWq_l = sym(g_Wq_l);
    void *pWk_h = sym(g_Wk_h), *pWk_l = sym(g_Wk_l);
    void *pWv_h = sym(g_Wv_h), *pWv_l = sym(g_Wv_l);
    void *pWo_h = sym(g_Wo_h), *pWo_l = sym(g_Wo_l);
    void *pWim_h = sym(g_Wim_h), *pWim_l = sym(g_Wim_l);

    cudaFuncSetAttribute(k_gemm3p,  cudaFuncAttributeMaxDynamicSharedMemorySize, GEMM_SMEM);
    cudaFuncSetAttribute(k_logits16,cudaFuncAttributeMaxDynamicSharedMemorySize, LOG_SMEM);
    cudaFuncSetAttribute(k_step,    cudaFuncAttributeMaxDynamicSharedMemorySize, STEP_SMEM);

    // ---- prep: weight conversions, embedding gather ----
    {
        int n = Vz*Gz;
        k_half<<<(n+255)/256, 256>>>(W_out, (__half*)pWoutf, n);
        n = G4z*Ez;
        k_split<<<(n+255)/256, 256>>>(W_ih, (bf16*)pWih_h, (bf16*)pWih_l, n);
        n = G4z*Gz;
        k_split<<<(n+255)/256, 256>>>(W_hh, (bf16*)pWhh_h, (bf16*)pWhh_l, n);
        k_bsum<<<(G4z+255)/256, 256>>>(b_ih, b_hh);
        n = MR*Ez;
        k_xgather<<<(n+255)/256, 256>>>(emb, sent);
        n = HIz*HIz;
        k_split<<<(n+255)/256, 256>>>(Wq, (bf16*)pWq_h, (bf16*)pWq_l, n);
        k_split<<<(n+255)/256, 256>>>(Wk, (bf16*)pWk_h, (bf16*)pWk_l, n);
        k_split<<<(n+255)/256, 256>>>(Wv, (bf16*)pWv_h, (bf16*)pWv_l, n);
        k_split<<<(n+255)/256, 256>>>(Wo, (bf16*)pWo_h, (bf16*)pWo_l, n);
        n = Ez*3*HIz;
        k_split<<<(n+255)/256, 256>>>(W_img, (bf16*)pWim_h, (bf16*)pWim_l, n);
        n = Bz*HIz;
        k_split<<<(n+255)/256, 256>>>(ent, (bf16*)pEnt_h, (bf16*)pEnt_l, n);
        n = Bz*16*HIz;
        k_split<<<(n+255)/256, 256>>>(neigh, (bf16*)pNei_h, (bf16*)pNei_l, n);
    }

    // ---- prologue: MHA + img_embed + first LSTM step (tensor-core GEMMs) ----
    {
        dim3 g1(1, HIz/128), g4(4, HIz/128);
        k_gemm3p<<<g1, 256, GEMM_SMEM>>>((bf16*)pEnt_h, (bf16*)pEnt_l,
            (bf16*)pWq_h, (bf16*)pWq_l, bq, (float*)pQ, Bz, HIz, HIz, 0);
        k_gemm3p<<<g4, 256, GEMM_SMEM>>>((bf16*)pNei_h, (bf16*)pNei_l,
            (bf16*)pWk_h, (bf16*)pWk_l, bk, (float*)pKb, Bz*16, HIz, HIz, 0);
        k_gemm3p<<<g4, 256, GEMM_SMEM>>>((bf16*)pNei_h, (bf16*)pNei_l,
            (bf16*)pWv_h, (bf16*)pWv_l, bv, (float*)pVb, Bz*16, HIz, HIz, 0);
        k_attn<<<Bz*8, 64>>>(nnum);
        int n = Bz*HIz;
        k_split<<<(n+255)/256, 256>>>((const float*)pCtx, (bf16*)pCtx_h, (bf16*)pCtx_l, n);
        k_gemm3p<<<g1, 256, GEMM_SMEM>>>((bf16*)pCtx_h, (bf16*)pCtx_l,
            (bf16*)pWo_h, (bf16*)pWo_l, bo, (float*)pAtt, Bz, HIz, HIz, 0);
        k_ff<<<(Bz*HIz+255)/256, 256>>>(ent, img);
        n = Bz*3*HIz;
        k_split<<<(n+255)/256, 256>>>((const float*)pFf, (bf16*)pFfs_h, (bf16*)pFfs_l, n);
        k_gemm3p<<<g1, 256, GEMM_SMEM>>>((bf16*)pFfs_h, (bf16*)pFfs_l,
            (bf16*)pWim_h, (bf16*)pWim_l, b_img, (float*)pIe, Bz, HIz, 3*HIz, 1);
        n = Bz*Ez;
        k_split<<<(n+255)/256, 256>>>((const float*)pIe, (bf16*)pIe_h, (bf16*)pIe_l, n);
        dim3 gg(1, G4z/128);
        k_gemm3p<<<gg, 256, GEMM_SMEM>>>((bf16*)pIe_h, (bf16*)pIe_l,
            (bf16*)pWih_h, (bf16*)pWih_l, (const float*)pBsum, (float*)pG0, Bz, G4z, Ez, 0);
        k_step0<<<(Bz*Gz+255)/256, 256>>>();
    }

    // ---- Xg = X @ W_ih^T + bsum for all 127 steps (one GEMM) ----
    {
        dim3 grid((MR+127)/128, G4z/128);
        k_gemm3p<<<grid, 256, GEMM_SMEM>>>((bf16*)pXh, (bf16*)pXl,
                               (bf16*)pWih_h, (bf16*)pWih_l,
                               (const float*)pBsum, (float*)pXg,
                               MR, G4z, Ez, 0);
    }

    // ---- recurrence: 127 fused steps, 128 blocks each ----
    for (int s = 0; s < Tz; s++)
        k_step<<<128, 128, STEP_SMEM>>>(s);

    // ---- logits: fp16 2-term [4064,1024]x[1024,32000], remap [B,T,V] ----
    {
        dim3 grid((MR+127)/128, Vz/128);   // 32 x 250
        k_logits16<<<grid, 256, LOG_SMEM>>>(
            (const __half*)pHf_h + Bz*Gz, (const __half*)pHf_l + Bz*Gz,
            (const __half*)pWoutf, b_out, out, MR, Vz, Gz);
    }

    // ---- tuple tail ----
    if ((long)out_size > (long)Bz*Tz*Vz)
        k_tail<<<(Bz*Sz+255)/256, 256>>>(sent, slen, out, (long)out_size);
}

// round 13
// speedup vs baseline: 1.8163x; 1.1711x over previous
#include <cuda_runtime.h>
#include <cuda_bf16.h>
#include <cuda_fp16.h>
#include <cstdint>

typedef __nv_bfloat16 bf16;

#define Bz   32
#define Sz   128
#define Tz   127
#define Vz   32000
#define Ez   512
#define Gz   1024
#define HIz  512
#define G4z  4096
#define MR   4064   /* Tz*Bz */

// ------------------------- static device scratch -------------------------
__device__ __half g_Woutf[(size_t)Vz*Gz];           // fp16 hi of W_out
__device__ bf16  g_Wih_hi[(size_t)G4z*Ez];
__device__ bf16  g_Wih_lo[(size_t)G4z*Ez];
__device__ bf16  g_Whh_hi[(size_t)G4z*Gz];
__device__ bf16  g_Whh_lo[(size_t)G4z*Gz];
__device__ bf16  g_H_hi[(size_t)(Tz+2)*Bz*Gz];      // bf16 h for recurrence
__device__ bf16  g_H_lo[(size_t)(Tz+2)*Bz*Gz];
__device__ __half g_Hf_hi[(size_t)(Tz+2)*Bz*Gz];    // fp16 h for logits
__device__ bf16  g_X_hi[(size_t)MR*Ez];
__device__ bf16  g_X_lo[(size_t)MR*Ez];
__device__ float g_Xg[(size_t)MR*G4z];
__device__ float g_c[Bz*Gz];
__device__ float g_Q[Bz*HIz];
__device__ float g_Kb[Bz*16*HIz];
__device__ float g_Vb[Bz*16*HIz];
__device__ float g_ctx[Bz*HIz];
__device__ float g_att[Bz*HIz];
__device__ float g_ff[Bz*3*HIz];
__device__ float g_ie[Bz*Ez];
__device__ float g_g0[Bz*G4z];
__device__ float g_bsum[G4z];
// prologue split buffers (bf16 hi/lo)
__device__ bf16 g_ent_h[Bz*HIz],   g_ent_l[Bz*HIz];
__device__ bf16 g_nei_h[Bz*16*HIz],g_nei_l[Bz*16*HIz];
__device__ bf16 g_ctx_h[Bz*HIz],   g_ctx_l[Bz*HIz];
__device__ bf16 g_ffs_h[Bz*3*HIz], g_ffs_l[Bz*3*HIz];
__device__ bf16 g_ie_h[Bz*Ez],     g_ie_l[Bz*Ez];
__device__ bf16 g_Wq_h[HIz*HIz],   g_Wq_l[HIz*HIz];
__device__ bf16 g_Wk_h[HIz*HIz],   g_Wk_l[HIz*HIz];
__device__ bf16 g_Wv_h[HIz*HIz],   g_Wv_l[HIz*HIz];
__device__ bf16 g_Wo_h[HIz*HIz],   g_Wo_l[HIz*HIz];
__device__ bf16 g_Wim_h[Ez*3*HIz], g_Wim_l[Ez*3*HIz];

// ------------------------------ helpers ----------------------------------
__device__ __forceinline__ float sigf(float x){ return 1.0f/(1.0f+expf(-x)); }

__device__ __forceinline__ uint32_t smem_u32(const void* p){
    return (uint32_t)__cvta_generic_to_shared(p);
}
__device__ __forceinline__ void ldsmx4(uint32_t* r, const void* p){
    uint32_t a = smem_u32(p);
    asm volatile("ldmatrix.sync.aligned.m8n8.x4.shared.b16 {%0,%1,%2,%3},[%4];\n"
                 : "=r"(r[0]),"=r"(r[1]),"=r"(r[2]),"=r"(r[3]) : "r"(a));
}
__device__ __forceinline__ void ldsmx2(uint32_t* r, const void* p){
    uint32_t a = smem_u32(p);
    asm volatile("ldmatrix.sync.aligned.m8n8.x2.shared.b16 {%0,%1},[%2];\n"
                 : "=r"(r[0]),"=r"(r[1]) : "r"(a));
}
__device__ __forceinline__ void mma_bf(float* d, const uint32_t* a, const uint32_t* b){
    asm volatile("mma.sync.aligned.m16n8k16.row.col.f32.bf16.bf16.f32 "
                 "{%0,%1,%2,%3},{%4,%5,%6,%7},{%8,%9},{%0,%1,%2,%3};\n"
                 : "+f"(d[0]),"+f"(d[1]),"+f"(d[2]),"+f"(d[3])
                 : "r"(a[0]),"r"(a[1]),"r"(a[2]),"r"(a[3]),
                   "r"(b[0]),"r"(b[1]));
}
__device__ __forceinline__ void mma_fp(float* d, const uint32_t* a, const uint32_t* b){
    asm volatile("mma.sync.aligned.m16n8k16.row.col.f32.f16.f16.f32 "
                 "{%0,%1,%2,%3},{%4,%5,%6,%7},{%8,%9},{%0,%1,%2,%3};\n"
                 : "+f"(d[0]),"+f"(d[1]),"+f"(d[2]),"+f"(d[3])
                 : "r"(a[0]),"r"(a[1]),"r"(a[2]),"r"(a[3]),
                   "r"(b[0]),"r"(b[1]));
}
#define CP_ASYNC16P(dst, src, pv) \
    asm volatile("cp.async.cg.shared.global [%0], [%1], 16, %2;" \
                 :: "r"(dst), "l"(src), "r"(pv))
#define CP_ASYNC16(dst, src) \
    asm volatile("cp.async.cg.shared.global [%0], [%1], 16;" :: "r"(dst), "l"(src))
#define CP_COMMIT()  asm volatile("cp.async.commit_group;" ::: "memory")

// --------------------------- prep kernels --------------------------------
__global__ void k_split(const float* __restrict__ src, bf16* __restrict__ hi,
                        bf16* __restrict__ lo, int n){
    int i = blockIdx.x*blockDim.x + threadIdx.x;
    if (i < n){
        float x = src[i];
        bf16 h = __float2bfloat16(x);
        hi[i] = h;
        lo[i] = __float2bfloat16(x - __bfloat162float(h));
    }
}
__global__ void k_half(const float* __restrict__ src, __half* __restrict__ dst, int n){
    int i = blockIdx.x*blockDim.x + threadIdx.x;
    if (i < n) dst[i] = __float2half(src[i]);
}
__global__ void k_bsum(const float* __restrict__ a, const float* __restrict__ b){
    int i = blockIdx.x*blockDim.x + threadIdx.x;
    if (i < G4z) g_bsum[i] = a[i] + b[i];
}
__global__ void k_xgather(const float* __restrict__ emb, const int* __restrict__ sent){
    int i = blockIdx.x*blockDim.x + threadIdx.x;
    if (i < MR*Ez){
        int r = i >> 9, col = i & 511;
        int t = r >> 5, b = r & 31;
        int idx = sent[b*Sz + t];
        float v = emb[(size_t)idx*Ez + col];
        bf16 h = __float2bfloat16(v);
        g_X_hi[i] = h;
        g_X_lo[i] = __float2bfloat16(v - __bfloat162float(h));
    }
}
__global__ void k_ff(const float* __restrict__ ent, const float* __restrict__ img){
    int i = blockIdx.x*blockDim.x + threadIdx.x;
    if (i < Bz*HIz){
        int b = i >> 9, j = i & 511;
        float* row = g_ff + (size_t)b*3*HIz;
        row[j]          = ent[i];
        row[HIz + j]    = g_att[i];
        row[2*HIz + j]  = img[i];
    }
}

// ------------------------------ attention --------------------------------
__global__ void k_attn(const int* __restrict__ nnum){
    int bh = blockIdx.x;
    int b = bh >> 3, h = bh & 7;
    int d = threadIdx.x;                    // 64 threads
    __shared__ float red[64];
    __shared__ float sc[16];
    float q = g_Q[b*HIz + h*64 + d];
    for (int n = 0; n < 16; n++){
        red[d] = q * g_Kb[(size_t)(b*16+n)*HIz + h*64 + d];
        __syncthreads();
        for (int o = 32; o; o >>= 1){
            if (d < o) red[d] += red[d+o];
            __syncthreads();
        }
        if (d == 0) sc[n] = red[0]*0.125f;
        __syncthreads();
    }
    int num = nnum[b];
    float a[16], mx = -1e30f;
#pragma unroll
    for (int n = 0; n < 16; n++){
        a[n] = (n >= num) ? -1e9f : sc[n];
        mx = fmaxf(mx, a[n]);
    }
    float ssum = 0.f;
#pragma unroll
    for (int n = 0; n < 16; n++){ a[n] = expf(a[n]-mx); ssum += a[n]; }
    float inv = 1.f/ssum;
    float ctx = 0.f;
#pragma unroll
    for (int n = 0; n < 16; n++)
        ctx += a[n] * g_Vb[(size_t)(b*16+n)*HIz + h*64 + d];
    g_ctx[b*HIz + h*64 + d] = ctx*inv;
}

// --------------------------- first LSTM step -----------------------------
__global__ void k_step0(){
    int i = blockIdx.x*blockDim.x + threadIdx.x;
    if (i < Bz*Gz){
        int b = i >> 10, j = i & 1023;
        const float* g0 = g_g0 + (size_t)b*G4z;
        float gi = g0[j], gg = g0[j+2*Gz], go = g0[j+3*Gz];
        float c = sigf(gi)*tanhf(gg);
        float h = sigf(go)*tanhf(c);
        g_c[i] = c;
        bf16 hh = __float2bfloat16(h);
        g_H_hi[i] = hh;
        g_H_lo[i] = __float2bfloat16(h - __bfloat162float(hh));
    }
}

// ---- fused recurrence step: 128 blocks x 128 thr, cp.async 3-stage ------
// Block nb owns gate cols {nb*8..+7} across all 4 quadrants (warp=quadrant).
#define SLD2 72
#define STEP_MAT (32*SLD2*2)     /* 4608 B per 32x64 bf16 matrix */
#define STEP_STG (4*STEP_MAT)    /* Ahi,Alo,Bhi,Blo = 18432 */
#define STEP_SMEM (3*STEP_STG)   /* 55296 */
__global__ void __launch_bounds__(128, 1) k_step(int s){
    extern __shared__ char dsm[];
    __shared__ float sG[4][32][8];
    const uint32_t sb = smem_u32(dsm);
    const int tid = threadIdx.x, warp = tid >> 5, lane = tid & 31;
    const int nb = blockIdx.x, c0 = nb*8;
    const bf16* hHi = g_H_hi + (size_t)s*Bz*Gz;
    const bf16* hLo = g_H_lo + (size_t)s*Bz*Gz;

    float acc[2][4];
#pragma unroll
    for (int a=0;a<2;a++)
#pragma unroll
    for (int c=0;c<4;c++) acc[a][c]=0.f;

    auto load_stage = [&](int ch, int buf){
        const int kk = ch*64;
        const uint32_t s0 = sb + buf*STEP_STG;
#pragma unroll
        for (int i = 0; i < 2; i++){
            int u = tid + i*128;
            int r = u >> 3, c = (u & 7)*8;
            uint32_t so = (uint32_t)((r*SLD2 + c)*2);
            CP_ASYNC16(s0 + so,              hHi + (size_t)r*Gz + kk + c);
            CP_ASYNC16(s0 + STEP_MAT + so,   hLo + (size_t)r*Gz + kk + c);
            int g = (r >> 3)*Gz + c0 + (r & 7);
            CP_ASYNC16(s0 + 2*STEP_MAT + so, g_Whh_hi + (size_t)g*Gz + kk + c);
            CP_ASYNC16(s0 + 3*STEP_MAT + so, g_Whh_lo + (size_t)g*Gz + kk + c);
        }
    };
    load_stage(0, 0); CP_COMMIT();
    load_stage(1, 1); CP_COMMIT();

    for (int ch = 0; ch < 16; ch++){
        asm volatile("cp.async.wait_group 1;" ::: "memory");
        __syncthreads();
        if (ch + 2 < 16) load_stage(ch + 2, (ch + 2) % 3);
        CP_COMMIT();
        const char* st = dsm + (ch % 3)*STEP_STG;
        const bf16* pA0 = (const bf16*)(st);
        const bf16* pA1 = (const bf16*)(st + STEP_MAT);
        const bf16* pB0 = (const bf16*)(st + 2*STEP_MAT);
        const bf16* pB1 = (const bf16*)(st + 3*STEP_MAT);
#pragma unroll
        for (int ks = 0; ks < 64; ks += 16){
            uint32_t ah[2][4], al[2][4], bh[2], bl[2];
#pragma unroll
            for (int mi = 0; mi < 2; mi++){
                int row = mi*16 + (lane & 15);
                int kc  = ks + (lane >> 4)*8;
                ldsmx4(ah[mi], pA0 + row*SLD2 + kc);
                ldsmx4(al[mi], pA1 + row*SLD2 + kc);
            }
            {
                int l = lane & 15;
                int row = warp*8 + (l & 7);
                int kc  = ks + ((l >> 3) & 1)*8;
                ldsmx2(bh, pB0 + row*SLD2 + kc);
                ldsmx2(bl, pB1 + row*SLD2 + kc);
            }
#pragma unroll
            for (int mi = 0; mi < 2; mi++){
                mma_bf(acc[mi], ah[mi], bh);
                mma_bf(acc[mi], ah[mi], bl);
                mma_bf(acc[mi], al[mi], bh);
            }
        }
    }
    // scatter: warp q holds quadrant q for (b, jl)
#pragma unroll
    for (int mi = 0; mi < 2; mi++)
#pragma unroll
    for (int h = 0; h < 2; h++){
        int b  = mi*16 + (lane >> 2) + h*8;
        int jl = (lane & 3)*2;
        sG[warp][b][jl]   = acc[mi][h*2];
        sG[warp][b][jl+1] = acc[mi][h*2+1];
    }
    __syncthreads();
    // LSTM cell update: 32x8 elements
    bf16* oHi = g_H_hi + (size_t)(s+1)*Bz*Gz;
    bf16* oLo = g_H_lo + (size_t)(s+1)*Bz*Gz;
    __half* fHi = g_Hf_hi + (size_t)(s+1)*Bz*Gz;
    const float* Xg = g_Xg + (size_t)s*Bz*G4z;
    for (int e = tid; e < 256; e += 128){
        int b = e >> 3, jl = e & 7;
        int col = c0 + jl;
        const float* xg = Xg + (size_t)b*G4z;
        float gi = sG[0][b][jl] + xg[col];
        float gf = sG[1][b][jl] + xg[col +   Gz];
        float gg = sG[2][b][jl] + xg[col + 2*Gz];
        float go = sG[3][b][jl] + xg[col + 3*Gz];
        float c = sigf(gf)*g_c[b*Gz+col] + sigf(gi)*tanhf(gg);
        float h = sigf(go)*tanhf(c);
        g_c[b*Gz+col] = c;
        bf16 hb = __float2bfloat16(h);
        oHi[b*Gz+col] = hb;
        oLo[b*Gz+col] = __float2bfloat16(h - __bfloat162float(hb));
        fHi[b*Gz+col] = __float2half(h);
    }
}

// ------ pipelined split-bf16 3-term GEMM (Xg + prologue), act 0/1=tanh ---
#define LDT   40
#define MATB  (128*LDT*2)
#define STGB  (4*MATB)
#define GEMM_SMEM (3*STGB)       /* 122880 */
__global__ void __launch_bounds__(256, 1) k_gemm3p(
    const bf16* __restrict__ Ahi, const bf16* __restrict__ Alo,
    const bf16* __restrict__ Bhi, const bf16* __restrict__ Blo,
    const float* __restrict__ bias, float* __restrict__ out,
    int M, int N, int K, int act)
{
    extern __shared__ char smem[];
    const uint32_t sb = smem_u32(smem);
    const int tid = threadIdx.x, warp = tid >> 5, lane = tid & 31;
    const int m0 = blockIdx.x*128, n0 = blockIdx.y*128;
    const int wm = (warp >> 2)*64, wn = (warp & 3)*32;
    const int NC = K >> 5;

    float acc[4][4][4];
#pragma unroll
    for (int a=0;a<4;a++)
#pragma unroll
    for (int b=0;b<4;b++)
#pragma unroll
    for (int c=0;c<4;c++) acc[a][b][c]=0.f;

    auto load_stage = [&](int chunk, int buf){
        const int kk = chunk << 5;
        const uint32_t s0 = sb + buf*STGB;
#pragma unroll
        for (int i = 0; i < 2; i++){
            int u = tid + i*256;
            int r = u >> 2, c = (u & 3)*8;
            uint32_t so = (uint32_t)((r*LDT + c)*2);
            int gr = m0 + r;
            uint32_t pv = (gr < M) ? 16u : 0u;
            int grc = gr < M ? gr : (M-1);
            CP_ASYNC16P(s0 + so,          Ahi + (size_t)grc*K + kk + c, pv);
            CP_ASYNC16P(s0 + MATB + so,   Alo + (size_t)grc*K + kk + c, pv);
            int gn = n0 + r;
            CP_ASYNC16(s0 + 2*MATB + so,  Bhi + (size_t)gn*K + kk + c);
            CP_ASYNC16(s0 + 3*MATB + so,  Blo + (size_t)gn*K + kk + c);
        }
    };
    load_stage(0, 0); CP_COMMIT();
    if (NC > 1){ load_stage(1, 1); } CP_COMMIT();

    for (int c = 0; c < NC; c++){
        asm volatile("cp.async.wait_group 1;" ::: "memory");
        __syncthreads();
        if (c + 2 < NC) load_stage(c + 2, (c + 2) % 3);
        CP_COMMIT();
        const char* st = smem + (c % 3)*STGB;
        const bf16* pA0 = (const bf16*)(st);
        const bf16* pA1 = (const bf16*)(st + MATB);
        const bf16* pB0 = (const bf16*)(st + 2*MATB);
        const bf16* pB1 = (const bf16*)(st + 3*MATB);
#pragma unroll
        for (int ks = 0; ks < 32; ks += 16){
            uint32_t ah[4][4], al[4][4], bh[2][4], bl[2][4];
#pragma unroll
            for (int mi = 0; mi < 4; mi++){
                int row = wm + mi*16 + (lane & 15);
                int kc  = ks + (lane >> 4)*8;
                ldsmx4(ah[mi], pA0 + row*LDT + kc);
                ldsmx4(al[mi], pA1 + row*LDT + kc);
            }
#pragma unroll
            for (int ni = 0; ni < 2; ni++){
                int j = lane >> 3;
                int row = wn + ni*16 + ((j >> 1)*8) + (lane & 7);
                int kc  = ks + (j & 1)*8;
                ldsmx4(bh[ni], pB0 + row*LDT + kc);
                ldsmx4(bl[ni], pB1 + row*LDT + kc);
            }
#pragma unroll
            for (int mi = 0; mi < 4; mi++)
#pragma unroll
                for (int nj = 0; nj < 4; nj++){
                    const uint32_t* fh = &bh[nj >> 1][(nj & 1)*2];
                    const uint32_t* fl = &bl[nj >> 1][(nj & 1)*2];
                    mma_bf(acc[mi][nj], ah[mi], fh);
                    mma_bf(acc[mi][nj], ah[mi], fl);
                    mma_bf(acc[mi][nj], al[mi], fh);
                }
        }
    }
#pragma unroll
    for (int mi = 0; mi < 4; mi++)
#pragma unroll
    for (int nj = 0; nj < 4; nj++){
        int n = n0 + wn + nj*8 + (lane & 3)*2;
        float b0 = bias[n], b1 = bias[n+1];
#pragma unroll
        for (int h = 0; h < 2; h++){
            int m = m0 + wm + mi*16 + (lane >> 2) + h*8;
            if (m < M){
                float v0 = acc[mi][nj][h*2]   + b0;
                float v1 = acc[mi][nj][h*2+1] + b1;
                if (act == 1){ v0 = tanhf(v0); v1 = tanhf(v1); }
                out[(size_t)m*N + n]   = v0;
                out[(size_t)m*N + n+1] = v1;
            }
        }
    }
}

// ---- logits: fp16 1-term pipelined GEMM, D = Ah @ Bh^T + bias -----------
// remap: row m = t*32+b  ->  out[(b*127+t)*Vz + n]
#define MATB2 (128*LDT*2)        /* 10240 */
#define STGB2 (2*MATB2)          /* Ah, Bh */
#define LOG_SMEM (3*STGB2)       /* 61440 */
__global__ void __launch_bounds__(256, 1) k_logits16(
    const __half* __restrict__ Ahi,
    const __half* __restrict__ Bhi,
    const float* __restrict__ bias, float* __restrict__ out,
    int M, int N, int K)
{
    extern __shared__ char smem[];
    const uint32_t sb = smem_u32(smem);
    const int tid = threadIdx.x, warp = tid >> 5, lane = tid & 31;
    const int m0 = blockIdx.x*128, n0 = blockIdx.y*128;
    const int wm = (warp >> 2)*64, wn = (warp & 3)*32;
    const int NC = K >> 5;

    float acc[4][4][4];
#pragma unroll
    for (int a=0;a<4;a++)
#pragma unroll
    for (int b=0;b<4;b++)
#pragma unroll
    for (int c=0;c<4;c++) acc[a][b][c]=0.f;

    auto load_stage = [&](int chunk, int buf){
        const int kk = chunk << 5;
        const uint32_t s0 = sb + buf*STGB2;
#pragma unroll
        for (int i = 0; i < 2; i++){
            int u = tid + i*256;
            int r = u >> 2, c = (u & 3)*8;
            uint32_t so = (uint32_t)((r*LDT + c)*2);
            int gr = m0 + r;
            uint32_t pv = (gr < M) ? 16u : 0u;
            int grc = gr < M ? gr : (M-1);
            CP_ASYNC16P(s0 + so,          Ahi + (size_t)grc*K + kk + c, pv);
            int gn = n0 + r;
            CP_ASYNC16(s0 + MATB2 + so,   Bhi + (size_t)gn*K + kk + c);
        }
    };
    load_stage(0, 0); CP_COMMIT();
    load_stage(1, 1); CP_COMMIT();

    for (int c = 0; c < NC; c++){
        asm volatile("cp.async.wait_group 1;" ::: "memory");
        __syncthreads();
        if (c + 2 < NC) load_stage(c + 2, (c + 2) % 3);
        CP_COMMIT();
        const char* st = smem + (c % 3)*STGB2;
        const __half* pA0 = (const __half*)(st);
        const __half* pB0 = (const __half*)(st + MATB2);
#pragma unroll
        for (int ks = 0; ks < 32; ks += 16){
            uint32_t ah[4][4], bh[2][4];
#pragma unroll
            for (int mi = 0; mi < 4; mi++){
                int row = wm + mi*16 + (lane & 15);
                int kc  = ks + (lane >> 4)*8;
                ldsmx4(ah[mi], pA0 + row*LDT + kc);
            }
#pragma unroll
            for (int ni = 0; ni < 2; ni++){
                int j = lane >> 3;
                int row = wn + ni*16 + ((j >> 1)*8) + (lane & 7);
                int kc  = ks + (j & 1)*8;
                ldsmx4(bh[ni], pB0 + row*LDT + kc);
            }
#pragma unroll
            for (int mi = 0; mi < 4; mi++)
#pragma unroll
                for (int nj = 0; nj < 4; nj++){
                    const uint32_t* fh = &bh[nj >> 1][(nj & 1)*2];
                    mma_fp(acc[mi][nj], ah[mi], fh);
                }
        }
    }
#pragma unroll
    for (int mi = 0; mi < 4; mi++)
#pragma unroll
    for (int nj = 0; nj < 4; nj++){
        int n = n0 + wn + nj*8 + (lane & 3)*2;
        float b0 = bias[n], b1 = bias[n+1];
#pragma unroll
        for (int h = 0; h < 2; h++){
            int m = m0 + wm + mi*16 + (lane >> 2) + h*8;
            if (m < M){
                int t = m >> 5, b = m & 31;
                size_t off = ((size_t)b*Tz + t)*(size_t)N + n;
                out[off]   = acc[mi][nj][h*2]   + b0;
                out[off+1] = acc[mi][nj][h*2+1] + b1;
            }
        }
    }
}

// ------------------------------- tail ------------------------------------
__global__ void k_tail(const int* __restrict__ sent, const int* __restrict__ slen,
                       float* __restrict__ out, long out_size){
    long base = (long)Bz*Tz*Vz;
    int i = blockIdx.x*blockDim.x + threadIdx.x;
    if (i < Bz*Sz && base + i < out_size)            out[base+i] = (float)sent[i];
    if (i < Bz && base + Bz*Sz + i < out_size)       out[base+Bz*Sz+i] = (float)slen[i];
}

// ------------------------------ host side --------------------------------
static inline void* sym(const void* s){ void* p; cudaGetSymbolAddress(&p, s); return p; }

extern "C" void kernel_launch(void* const* d_in, const int* in_sizes, int n_in,
                              void* d_out, int out_size) {
    const float* ent   = (const float*)d_in[0];
    const float* neigh = (const float*)d_in[1];
    const int*   nnum  = (const int*)  d_in[2];
    const float* img   = (const float*)d_in[3];
    const int*   sent  = (const int*)  d_in[4];
    const int*   slen  = (const int*)  d_in[5];
    const float* emb   = (const float*)d_in[6];
    const float* W_ih  = (const float*)d_in[7];
    const float* W_hh  = (const float*)d_in[8];
    const float* b_ih  = (const float*)d_in[9];
    const float* b_hh  = (const float*)d_in[10];
    const float* W_img = (const float*)d_in[11];
    const float* b_img = (const float*)d_in[12];
    const float* W_out = (const float*)d_in[13];
    const float* b_out = (const float*)d_in[14];
    const float* Wq = (const float*)d_in[15]; const float* bq = (const float*)d_in[16];
    const float* Wk = (const float*)d_in[17]; const float* bk = (const float*)d_in[18];
    const float* Wv = (const float*)d_in[19]; const float* bv = (const float*)d_in[20];
    const float* Wo = (const float*)d_in[21]; const float* bo = (const float*)d_in[22];
    float* out = (float*)d_out;

    void *pWoutf = sym(g_Woutf);
    void *pWih_h = sym(g_Wih_hi), *pWih_l = sym(g_Wih_lo);
    void *pWhh_h = sym(g_Whh_hi), *pWhh_l = sym(g_Whh_lo);
    void *pHf_h = sym(g_Hf_hi);
    void *pXh = sym(g_X_hi), *pXl = sym(g_X_lo);
    void *pXg = sym(g_Xg), *pBsum = sym(g_bsum);
    void *pQ = sym(g_Q), *pKb = sym(g_Kb), *pVb = sym(g_Vb);
    void *pCtx = sym(g_ctx), *pAtt = sym(g_att), *pFf = sym(g_ff);
    void *pIe = sym(g_ie), *pG0 = sym(g_g0);
    void *pEnt_h = sym(g_ent_h), *pEnt_l = sym(g_ent_l);
    void *pNei_h = sym(g_nei_h), *pNei_l = sym(g_nei_l);
    void *pCtx_h = sym(g_ctx_h), *pCtx_l = sym(g_ctx_l);
    void *pFfs_h = sym(g_ffs_h), *pFfs_l = sym(g_ffs_l);
    void *pIe_h = sym(g_ie_h), *pIe_l = sym(g_ie_l);
    void *pWq_h = sym(g_Wq_h), *pWq_l = sym(g_Wq_l);
    void *pWk_h = sym(g_Wk_h), *pWk_l = sym(g_Wk_l);
    void *pWv_h = sym(g_Wv_h), *pWv_l = sym(g_Wv_l);
    void *pWo_h = sym(g_Wo_h), *pWo_l = sym(g_Wo_l);
    void *pWim_h = sym(g_Wim_h), *pWim_l = sym(g_Wim_l);

    cudaFuncSetAttribute(k_gemm3p,  cudaFuncAttributeMaxDynamicSharedMemorySize, GEMM_SMEM);
    cudaFuncSetAttribute(k_logits16,cudaFuncAttributeMaxDynamicSharedMemorySize, LOG_SMEM);
    cudaFuncSetAttribute(k_step,    cudaFuncAttributeMaxDynamicSharedMemorySize, STEP_SMEM);

    // ---- prep: weight conversions, embedding gather ----
    {
        int n = Vz*Gz;
        k_half<<<(n+255)/256, 256>>>(W_out, (__half*)pWoutf, n);
        n = G4z*Ez;
        k_split<<<(n+255)/256, 256>>>(W_ih, (bf16*)pWih_h, (bf16*)pWih_l, n);
        n = G4z*Gz;
        k_split<<<(n+255)/256, 256>>>(W_hh, (bf16*)pWhh_h, (bf16*)pWhh_l, n);
        k_bsum<<<(G4z+255)/256, 256>>>(b_ih, b_hh);
        n = MR*Ez;
        k_xgather<<<(n+255)/256, 256>>>(emb, sent);
        n = HIz*HIz;
        k_split<<<(n+255)/256, 256>>>(Wq, (bf16*)pWq_h, (bf16*)pWq_l, n);
        k_split<<<(n+255)/256, 256>>>(Wk, (bf16*)pWk_h, (bf16*)pWk_l, n);
        k_split<<<(n+255)/256, 256>>>(Wv, (bf16*)pWv_h, (bf16*)pWv_l, n);
        k_split<<<(n+255)/256, 256>>>(Wo, (bf16*)pWo_h, (bf16*)pWo_l, n);
        n = Ez*3*HIz;
        k_split<<<(n+255)/256, 256>>>(W_img, (bf16*)pWim_h, (bf16*)pWim_l, n);
        n = Bz*HIz;
        k_split<<<(n+255)/256, 256>>>(ent, (bf16*)pEnt_h, (bf16*)pEnt_l, n);
        n = Bz*16*HIz;
        k_split<<<(n+255)/256, 256>>>(neigh, (bf16*)pNei_h, (bf16*)pNei_l, n);
    }

    // ---- prologue: MHA + img_embed + first LSTM step (tensor-core GEMMs) ----
    {
        dim3 g1(1, HIz/128), g4(4, HIz/128);
        k_gemm3p<<<g1, 256, GEMM_SMEM>>>((bf16*)pEnt_h, (bf16*)pEnt_l,
            (bf16*)pWq_h, (bf16*)pWq_l, bq, (float*)pQ, Bz, HIz, HIz, 0);
        k_gemm3p<<<g4, 256, GEMM_SMEM>>>((bf16*)pNei_h, (bf16*)pNei_l,
            (bf16*)pWk_h, (bf16*)pWk_l, bk, (float*)pKb, Bz*16, HIz, HIz, 0);
        k_gemm3p<<<g4, 256, GEMM_SMEM>>>((bf16*)pNei_h, (bf16*)pNei_l,
            (bf16*)pWv_h, (bf16*)pWv_l, bv, (float*)pVb, Bz*16, HIz, HIz, 0);
        k_attn<<<Bz*8, 64>>>(nnum);
        int n = Bz*HIz;
        k_split<<<(n+255)/256, 256>>>((const float*)pCtx, (bf16*)pCtx_h, (bf16*)pCtx_l, n);
        k_gemm3p<<<g1, 256, GEMM_SMEM>>>((bf16*)pCtx_h, (bf16*)pCtx_l,
            (bf16*)pWo_h, (bf16*)pWo_l, bo, (float*)pAtt, Bz, HIz, HIz, 0);
        k_ff<<<(Bz*HIz+255)/256, 256>>>(ent, img);
        n = Bz*3*HIz;
        k_split<<<(n+255)/256, 256>>>((const float*)pFf, (bf16*)pFfs_h, (bf16*)pFfs_l, n);
        k_gemm3p<<<g1, 256, GEMM_SMEM>>>((bf16*)pFfs_h, (bf16*)pFfs_l,
            (bf16*)pWim_h, (bf16*)pWim_l, b_img, (float*)pIe, Bz, HIz, 3*HIz, 1);
        n = Bz*Ez;
        k_split<<<(n+255)/256, 256>>>((const float*)pIe, (bf16*)pIe_h, (bf16*)pIe_l, n);
        dim3 gg(1, G4z/128);
        k_gemm3p<<<gg, 256, GEMM_SMEM>>>((bf16*)pIe_h, (bf16*)pIe_l,
            (bf16*)pWih_h, (bf16*)pWih_l, (const float*)pBsum, (float*)pG0, Bz, G4z, Ez, 0);
        k_step0<<<(Bz*Gz+255)/256, 256>>>();
    }

    // ---- Xg = X @ W_ih^T + bsum for all 127 steps (one GEMM) ----
    {
        dim3 grid((MR+127)/128, G4z/128);
        k_gemm3p<<<grid, 256, GEMM_SMEM>>>((bf16*)pXh, (bf16*)pXl,
                               (bf16*)pWih_h, (bf16*)pWih_l,
                               (const float*)pBsum, (float*)pXg,
                               MR, G4z, Ez, 0);
    }

    // ---- recurrence: 127 fused steps, 128 blocks each ----
    for (int s = 0; s < Tz; s++)
        k_step<<<128, 128, STEP_SMEM>>>(s);

    // ---- logits: fp16 1-term [4064,1024]x[1024,32000], remap [B,T,V] ----
    {
        dim3 grid((MR+127)/128, Vz/128);   // 32 x 250
        k_logits16<<<grid, 256, LOG_SMEM>>>(
            (const __half*)pHf_h + Bz*Gz,
            (const __half*)pWoutf, b_out, out, MR, Vz, Gz);
    }

    // ---- tuple tail ----
    if ((long)out_size > (long)Bz*Tz*Vz)
        k_tail<<<(Bz*Sz+255)/256, 256>>>(sent, slen, out, (long)out_size);
}